// round 13
// baseline (speedup 1.0000x reference)
#include <cuda_runtime.h>
#include <math.h>

#define NN 4096
#define NPTS 32768
#define SLICES 4
#define SLICE_N 1024

typedef unsigned long long ull;

__device__ __forceinline__ ull pack2(float v) {
    ull r; unsigned u = __float_as_uint(v);
    asm("mov.b64 %0,{%1,%1};" : "=l"(r) : "r"(u));
    return r;
}
__device__ __forceinline__ ull pack2f(float lo, float hi) {
    ull r;
    asm("mov.b64 %0,{%1,%2};" : "=l"(r) : "r"(__float_as_uint(lo)), "r"(__float_as_uint(hi)));
    return r;
}
__device__ __forceinline__ void ffma2(ull &d, ull a, ull b) {
    asm("fma.rn.f32x2 %0, %1, %2, %0;" : "+l"(d) : "l"(a), "l"(b));
}
__device__ __forceinline__ ull mul2(ull a, ull b) {
    ull r; asm("mul.rn.f32x2 %0, %1, %2;" : "=l"(r) : "l"(a), "l"(b)); return r;
}
__device__ __forceinline__ ull add2(ull a, ull b) {
    ull r; asm("add.rn.f32x2 %0, %1, %2;" : "=l"(r) : "l"(a), "l"(b)); return r;
}
__device__ __forceinline__ ull fma2v(ull a, ull b, ull c) {
    ull r; asm("fma.rn.f32x2 %0, %1, %2, %3;" : "=l"(r) : "l"(a), "l"(b), "l"(c)); return r;
}
__device__ __forceinline__ float lo2(ull v) { return __uint_as_float((unsigned)v); }
__device__ __forceinline__ float hi2(ull v) { return __uint_as_float((unsigned)(v >> 32)); }

// scratch (static __device__, no allocation)
__device__ float g_lcc[NPTS * 10];        // (pt, k, xy)
__device__ float g_lf [NPTS * 64];        // local_feats
__device__ float g_pd [NPTS * 20];        // partial top-5 dists, 4 slices
__device__ int   g_pi [NPTS * 20];        // partial top-5 indices

// out layout: [cls 32768*128 | topo 32768*128 | angle 32768 | axes 32768*2]
#define OFF_TOPO 4194304
#define OFF_ANG  8388608
#define OFF_AX   8421376

// insert (dd, mi) into sorted-ascending register top-5 with strict < (stable by index)
#define INS5(dd, mi)                                                        \
    if (dd < d4) {                                                          \
        if (dd < d3) {                                                      \
            d4 = d3; i4 = i3;                                               \
            if (dd < d2) {                                                  \
                d3 = d2; i3 = i2;                                           \
                if (dd < d1) {                                              \
                    d2 = d1; i2 = i1;                                       \
                    if (dd < d0) { d1 = d0; i1 = i0; d0 = dd; i0 = mi; }    \
                    else          { d1 = dd; i1 = mi; }                     \
                } else { d2 = dd; i2 = mi; }                                \
            } else { d3 = dd; i3 = mi; }                                    \
        } else { d4 = dd; i4 = mi; }                                        \
    }

// ---------------- Kernel A1: partial KNN over one candidate slice (packed f32x2) ----------------
__global__ __launch_bounds__(128)
void knn_part_kernel(const float* __restrict__ xg)
{
    __shared__ ull sx[SLICE_N / 2];   // packed x pairs
    __shared__ ull sy[SLICE_N / 2];   // packed y pairs
    __shared__ ull sq[SLICE_N / 2];   // packed sq pairs

    const int b  = blockIdx.z;
    const int s  = blockIdx.y;
    const int m0 = s * SLICE_N;
    const float2* xb = reinterpret_cast<const float2*>(xg) + (size_t)b * NN;

    for (int i = threadIdx.x; i < SLICE_N / 2; i += 128) {
        float2 p0 = xb[m0 + 2*i];
        float2 p1 = xb[m0 + 2*i + 1];
        sx[i] = pack2f(p0.x, p1.x);
        sy[i] = pack2f(p0.y, p1.y);
        // sq = rn(x*x) + rn(y*y)  (jnp.sum(x*x,-1), no fma)
        float q0 = __fadd_rn(__fmul_rn(p0.x, p0.x), __fmul_rn(p0.y, p0.y));
        float q1 = __fadd_rn(__fmul_rn(p1.x, p1.x), __fmul_rn(p1.y, p1.y));
        sq[i] = pack2f(q0, q1);
    }
    __syncthreads();

    const int n = blockIdx.x * 128 + threadIdx.x;
    float2 qv = xb[n];
    const float sqn = __fadd_rn(__fmul_rn(qv.x, qv.x), __fmul_rn(qv.y, qv.y));
    const ull QX = pack2(qv.x), QY = pack2(qv.y), SQN = pack2(sqn), NEG2 = pack2(-2.0f);

    float d0 = 3.4e38f, d1 = 3.4e38f, d2 = 3.4e38f, d3 = 3.4e38f, d4 = 3.4e38f;
    int   i0 = 0, i1 = 0, i2 = 0, i3 = 0, i4 = 0;

    #pragma unroll 4
    for (int j = 0; j < SLICE_N / 2; ++j) {
        ull X = sx[j], Y = sy[j], S = sq[j];
        // dot = fma(y, qy, rn(x*qx))  (Eigen k=2 fold), dd = rn(sum - 2*dot)
        ull dot = fma2v(Y, QY, mul2(X, QX));
        ull sum = add2(SQN, S);
        ull ddp = fma2v(dot, NEG2, sum);   // exact: 2*dot has no rounding
        float ddlo = lo2(ddp), ddhi = hi2(ddp);
        int mi = m0 + 2*j;
        INS5(ddlo, mi);
        INS5(ddhi, mi + 1);
    }

    float* pd = g_pd + ((size_t)(b * NN + n)) * 20 + s * 5;
    int*   pi = g_pi + ((size_t)(b * NN + n)) * 20 + s * 5;
    pd[0] = d0; pd[1] = d1; pd[2] = d2; pd[3] = d3; pd[4] = d4;
    pi[0] = i0; pi[1] = i1; pi[2] = i2; pi[3] = i3; pi[4] = i4;
}

// ---------------- Kernel A2: merge partials + slaev2 eigh + lcc ----------------
__global__ __launch_bounds__(128)
void knn_merge_geom_kernel(const float* __restrict__ xg, float* __restrict__ out)
{
    const int pt = blockIdx.x * 128 + threadIdx.x;
    const int b  = pt >> 12;
    const int n  = pt & (NN - 1);
    const float2* xb = reinterpret_cast<const float2*>(xg) + (size_t)b * NN;

    float pd[20]; int pi[20];
    {
        const float* gp = g_pd + (size_t)pt * 20;
        const int*   gi = g_pi + (size_t)pt * 20;
        #pragma unroll
        for (int j = 0; j < 20; ++j) { pd[j] = gp[j]; pi[j] = gi[j]; }
    }

    // exact global top-5 by (d, idx) lexicographic (== lax.top_k stable order)
    int nb[5];
    unsigned used = 0;
    #pragma unroll
    for (int k = 0; k < 5; ++k) {
        float best = 3.5e38f; int bidx = 0x7fffffff; int bj = 0;
        #pragma unroll
        for (int j = 0; j < 20; ++j) {
            bool freej = !((used >> j) & 1u);
            float dj = pd[j]; int ij = pi[j];
            if (freej && (dj < best || (dj == best && ij < bidx))) {
                best = dj; bidx = ij; bj = j;
            }
        }
        used |= 1u << bj;
        nb[k] = bidx;
    }

    const float qx = xb[n].x, qy = xb[n].y;
    float rx[5], ry[5];
    #pragma unroll
    for (int k = 0; k < 5; ++k) {
        float2 p = xb[nb[k]];
        rx[k] = __fsub_rn(p.x, qx);
        ry[k] = __fsub_rn(p.y, qy);
    }
    float sxs = __fadd_rn(__fadd_rn(__fadd_rn(__fadd_rn(rx[0], rx[1]), rx[2]), rx[3]), rx[4]);
    float sys = __fadd_rn(__fadd_rn(__fadd_rn(__fadd_rn(ry[0], ry[1]), ry[2]), ry[3]), ry[4]);
    float mx = __fdiv_rn(sxs, 5.0f);
    float my = __fdiv_rn(sys, 5.0f);
    float cx[5], cy[5];
    float sxx = 0.f, sxy = 0.f, syy = 0.f;
    #pragma unroll
    for (int k = 0; k < 5; ++k) {
        cx[k] = __fsub_rn(rx[k], mx);
        cy[k] = __fsub_rn(ry[k], my);
        sxx = __fmaf_rn(cx[k], cx[k], sxx);
        sxy = __fmaf_rn(cx[k], cy[k], sxy);
        syy = __fmaf_rn(cy[k], cy[k], syy);
    }
    float a  = __fadd_rn(__fmul_rn(sxx, 0.25f), 1e-6f);
    float bv = __fmul_rn(sxy, 0.25f);
    float c  = __fadd_rn(__fmul_rn(syy, 0.25f), 1e-6f);

    // ---- LAPACK slaev2 (a,c > 0 => sm > 0 => sgn1 = +1) ----
    float smv = a + c, df = a - c;
    float adf = fabsf(df);
    float tb  = bv + bv;
    float ab  = fabsf(tb);
    float rt;
    if (adf > ab)      { float t = ab / adf; rt = adf * sqrtf(1.f + t*t); }
    else if (adf < ab) { float t = adf / ab; rt = ab * sqrtf(1.f + t*t); }
    else               { rt = ab * 1.4142135623730951f; }
    float rt1 = 0.5f * (smv + rt);
    float acmx, acmn;
    if (fabsf(a) > fabsf(c)) { acmx = a; acmn = c; } else { acmx = c; acmn = a; }
    float rt2 = (acmx / rt1) * acmn - (bv / rt1) * bv;
    float cs; int sgn2;
    if (df >= 0.f) { cs = df + rt; sgn2 = 1; }
    else           { cs = df - rt; sgn2 = -1; }
    float acs = fabsf(cs), cs1, sn1;
    if (acs > ab)       { float ct = -tb / cs; sn1 = 1.f / sqrtf(1.f + ct*ct); cs1 = ct * sn1; }
    else if (ab == 0.f) { cs1 = 1.f; sn1 = 0.f; }
    else                { float tn = -cs / tb; cs1 = 1.f / sqrtf(1.f + tn*tn); sn1 = tn * cs1; }
    if (sgn2 == 1)      { float t = cs1; cs1 = -sn1; sn1 = t; }

    float e0, e1, v00, v10, v01, v11;
    if (rt2 < rt1) { e0 = rt2; e1 = rt1; v00 = -sn1; v10 = cs1; v01 = cs1;  v11 = sn1; }
    else           { e0 = rt1; e1 = rt2; v00 = cs1;  v10 = sn1; v01 = -sn1; v11 = cs1; }

    out[OFF_ANG + pt] = atan2f(v11, v01);
    float sL = sqrtf(fmaxf(e1, 1e-6f));
    float sS = sqrtf(fmaxf(e0, 1e-6f));
    float den = fmaxf(sL, sS) + 1e-6f;
    out[OFF_AX + pt * 2 + 0] = fmaxf(sL / den, 0.2f);
    out[OFF_AX + pt * 2 + 1] = fmaxf(sS / den, 0.2f);

    float* lp = g_lcc + (size_t)pt * 10;
    #pragma unroll
    for (int k = 0; k < 5; ++k) {
        lp[2*k]   = __fmaf_rn(cy[k], v10, __fmul_rn(cx[k], v00));
        lp[2*k+1] = __fmaf_rn(cy[k], v11, __fmul_rn(cx[k], v01));
    }
}

// ---------------- Kernel B: local MLP 2->64->128->64 + max over K ----------------
// 32 points/CTA (160 rows), 1024 threads (32 warps). Weight loads warp-uniform.
#define B_SMEM_FLOATS (27392 + 160*133)
__global__ __launch_bounds__(1024)
void local_mlp_kernel(const float* __restrict__ lw1, const float* __restrict__ lb1,
                      const float* __restrict__ lw2, const float* __restrict__ lb2,
                      const float* __restrict__ lw3, const float* __restrict__ lb3)
{
    extern __shared__ float smf[];
    float* w1s  = smf;
    float* b1s  = smf + 128;
    float* w2s  = smf + 192;
    float* b2s  = smf + 8384;
    float* w3s  = smf + 8512;
    float* b3s  = smf + 16704;
    float* lccs = smf + 16768;
    float* h1T  = smf + 17088;   // [64][161]  k-major
    float* h2s  = smf + 27392;   // [160][133]

    const int tid  = threadIdx.x;
    const int base = blockIdx.x * 32;

    for (int i = tid; i < 128;  i += 1024) { w1s[i] = lw1[i]; b2s[i] = lb2[i]; }
    for (int i = tid; i < 64;   i += 1024) { b1s[i] = lb1[i]; b3s[i] = lb3[i]; }
    for (int i = tid; i < 8192; i += 1024) { w2s[i] = lw2[i]; w3s[i] = lw3[i]; }
    if (tid < 320) lccs[tid] = g_lcc[(size_t)base * 10 + tid];
    __syncthreads();

    // stage 1: h1 (160x64) -> h1T[c*161 + r]
    for (int idx = tid; idx < 160 * 64; idx += 1024) {
        int r = idx >> 6, c = idx & 63;
        float v = fmaf(lccs[2*r], w1s[c], fmaf(lccs[2*r+1], w1s[64 + c], b1s[c]));
        h1T[c * 161 + r] = fmaxf(v, 0.f);
    }
    __syncthreads();

    const int rg = tid & 31;       // point (lane)
    const int cg = tid >> 5;       // 0..31 (warp-uniform)
    const int r0 = rg * 5;

    // stage 2: h2 (160x128), tile 5 rows x 4 cols, weight = 1 warp-uniform LDS.128
    {
        const int c0 = cg * 4;
        ull acc[5][2];
        ulonglong2 bp = *reinterpret_cast<const ulonglong2*>(b2s + c0);
        #pragma unroll
        for (int j = 0; j < 5; ++j) { acc[j][0] = bp.x; acc[j][1] = bp.y; }
        #pragma unroll 2
        for (int k = 0; k < 64; ++k) {
            ull av[5];
            #pragma unroll
            for (int j = 0; j < 5; ++j) av[j] = pack2(h1T[k * 161 + r0 + j]);
            ulonglong2 w = *reinterpret_cast<const ulonglong2*>(w2s + k*128 + c0);
            #pragma unroll
            for (int j = 0; j < 5; ++j) {
                ffma2(acc[j][0], av[j], w.x);
                ffma2(acc[j][1], av[j], w.y);
            }
        }
        #pragma unroll
        for (int j = 0; j < 5; ++j) {
            float* hp = h2s + (r0 + j) * 133 + c0;
            hp[0] = fmaxf(lo2(acc[j][0]), 0.f);
            hp[1] = fmaxf(hi2(acc[j][0]), 0.f);
            hp[2] = fmaxf(lo2(acc[j][1]), 0.f);
            hp[3] = fmaxf(hi2(acc[j][1]), 0.f);
        }
    }
    __syncthreads();

    // stage 3: h3 (160x64), tile 5 rows x 2 cols, fused relu+max over 5 neighbors
    {
        const int c0 = cg * 2;
        ull acc3[5];
        ull bp = *reinterpret_cast<const ull*>(b3s + c0);
        #pragma unroll
        for (int j = 0; j < 5; ++j) acc3[j] = bp;
        #pragma unroll 2
        for (int k = 0; k < 128; ++k) {
            ull w = *reinterpret_cast<const ull*>(w3s + k*64 + c0);
            #pragma unroll
            for (int j = 0; j < 5; ++j) {
                ull av = pack2(h2s[(r0 + j) * 133 + k]);
                ffma2(acc3[j], av, w);
            }
        }
        float mlo = 0.f, mhi = 0.f;   // relu floor
        #pragma unroll
        for (int j = 0; j < 5; ++j) {
            mlo = fmaxf(mlo, lo2(acc3[j]));
            mhi = fmaxf(mhi, hi2(acc3[j]));
        }
        *reinterpret_cast<float2*>(g_lf + (size_t)(base + rg) * 64 + c0) = make_float2(mlo, mhi);
    }
}

// ---------------- Kernel C: BOTH heads, 128 points/CTA, 1024 threads ----------------
// thread tile: 1 point x 16 cols; weight LDS warp-uniform broadcast.
template<int INDIM>
__device__ __forceinline__ void head_body(
    const float* __restrict__ w1s, const float* __restrict__ b1s,
    const float* __restrict__ w2s, const float* __restrict__ b2s,
    const float* __restrict__ ins, float* __restrict__ hs,
    float* __restrict__ outp, int base, int tid)
{
    const int p  = tid & 127;         // point
    const int c0 = (tid >> 7) * 16;   // warp-uniform column base

    // stage 1: 128 x 128, tile 1 row x 16 cols
    {
        ull acc[8];
        ulonglong2 bq0 = *reinterpret_cast<const ulonglong2*>(b1s + c0);
        ulonglong2 bq1 = *reinterpret_cast<const ulonglong2*>(b1s + c0 + 4);
        ulonglong2 bq2 = *reinterpret_cast<const ulonglong2*>(b1s + c0 + 8);
        ulonglong2 bq3 = *reinterpret_cast<const ulonglong2*>(b1s + c0 + 12);
        acc[0]=bq0.x; acc[1]=bq0.y; acc[2]=bq1.x; acc[3]=bq1.y;
        acc[4]=bq2.x; acc[5]=bq2.y; acc[6]=bq3.x; acc[7]=bq3.y;
        #pragma unroll 2
        for (int k = 0; k < INDIM; ++k) {
            ull a = pack2(ins[p * 67 + k]);
            const float* wr = w1s + k * 128 + c0;
            ulonglong2 w0 = *reinterpret_cast<const ulonglong2*>(wr);
            ulonglong2 w1q = *reinterpret_cast<const ulonglong2*>(wr + 4);
            ulonglong2 w2q = *reinterpret_cast<const ulonglong2*>(wr + 8);
            ulonglong2 w3q = *reinterpret_cast<const ulonglong2*>(wr + 12);
            ffma2(acc[0], a, w0.x);  ffma2(acc[1], a, w0.y);
            ffma2(acc[2], a, w1q.x); ffma2(acc[3], a, w1q.y);
            ffma2(acc[4], a, w2q.x); ffma2(acc[5], a, w2q.y);
            ffma2(acc[6], a, w3q.x); ffma2(acc[7], a, w3q.y);
        }
        float* hp = hs + p * 131 + c0;
        #pragma unroll
        for (int i = 0; i < 8; ++i) {
            hp[2*i]   = fmaxf(lo2(acc[i]), 0.f);
            hp[2*i+1] = fmaxf(hi2(acc[i]), 0.f);
        }
    }
    __syncthreads();

    // stage 2: 128 x 128
    {
        ull acc[8];
        ulonglong2 bq0 = *reinterpret_cast<const ulonglong2*>(b2s + c0);
        ulonglong2 bq1 = *reinterpret_cast<const ulonglong2*>(b2s + c0 + 4);
        ulonglong2 bq2 = *reinterpret_cast<const ulonglong2*>(b2s + c0 + 8);
        ulonglong2 bq3 = *reinterpret_cast<const ulonglong2*>(b2s + c0 + 12);
        acc[0]=bq0.x; acc[1]=bq0.y; acc[2]=bq1.x; acc[3]=bq1.y;
        acc[4]=bq2.x; acc[5]=bq2.y; acc[6]=bq3.x; acc[7]=bq3.y;
        #pragma unroll 2
        for (int k = 0; k < 128; ++k) {
            ull a = pack2(hs[p * 131 + k]);
            const float* wr = w2s + k * 128 + c0;
            ulonglong2 w0 = *reinterpret_cast<const ulonglong2*>(wr);
            ulonglong2 w1q = *reinterpret_cast<const ulonglong2*>(wr + 4);
            ulonglong2 w2q = *reinterpret_cast<const ulonglong2*>(wr + 8);
            ulonglong2 w3q = *reinterpret_cast<const ulonglong2*>(wr + 12);
            ffma2(acc[0], a, w0.x);  ffma2(acc[1], a, w0.y);
            ffma2(acc[2], a, w1q.x); ffma2(acc[3], a, w1q.y);
            ffma2(acc[4], a, w2q.x); ffma2(acc[5], a, w2q.y);
            ffma2(acc[6], a, w3q.x); ffma2(acc[7], a, w3q.y);
        }
        float* op = outp + (size_t)(base + p) * 128 + c0;
        #pragma unroll
        for (int i = 0; i < 8; ++i) {
            float2 v = make_float2(fmaxf(lo2(acc[i]), 0.f), fmaxf(hi2(acc[i]), 0.f));
            *reinterpret_cast<float2*>(op + 2*i) = v;
        }
    }
}

// smem: w1s 8448 | b1s 128 | w2s 16384 | b2s 128 | ins 128*67 | hs 128*131
#define H_SMEM_FLOATS (8448 + 128 + 16384 + 128 + 128*67 + 128*131)
__global__ __launch_bounds__(1024)
void head2_kernel(const float* __restrict__ xg,
                  const float* __restrict__ cw1, const float* __restrict__ cb1,
                  const float* __restrict__ cw2, const float* __restrict__ cb2,
                  const float* __restrict__ tw1, const float* __restrict__ tb1,
                  const float* __restrict__ tw2, const float* __restrict__ tb2,
                  float* __restrict__ outg)
{
    extern __shared__ float smf[];
    float* w1s = smf;
    float* b1s = smf + 8448;
    float* w2s = smf + 8576;
    float* b2s = smf + 24960;
    float* ins = smf + 25088;   // [128][67]
    float* hs  = smf + 33664;   // [128][131]

    const int head = blockIdx.y;
    const float* w1 = head ? tw1 : cw1;
    const float* b1 = head ? tb1 : cb1;
    const float* w2 = head ? tw2 : cw2;
    const float* b2 = head ? tb2 : cb2;
    const int indim = head ? 64 : 66;
    const int xoff  = head ? 0 : 2;
    float* outp = outg + (head ? OFF_TOPO : 0);

    const int tid  = threadIdx.x;
    const int base = blockIdx.x * 128;

    for (int i = tid; i < indim * 128; i += 1024) w1s[i] = w1[i];
    for (int i = tid; i < 16384;       i += 1024) w2s[i] = w2[i];
    if (tid < 128) { b1s[tid] = b1[tid]; b2s[tid] = b2[tid]; }
    for (int idx = tid; idx < 128 * 64; idx += 1024) {
        int p = idx >> 6, c = idx & 63;
        ins[p * 67 + xoff + c] = g_lf[(size_t)(base + p) * 64 + c];
    }
    if (!head && tid < 256) {
        int p = tid >> 1, c = tid & 1;
        ins[p * 67 + c] = xg[(size_t)(base + p) * 2 + c];
    }
    __syncthreads();

    if (head) head_body<64>(w1s, b1s, w2s, b2s, ins, hs, outp, base, tid);
    else      head_body<66>(w1s, b1s, w2s, b2s, ins, hs, outp, base, tid);
}

// ---------------- launch ----------------
extern "C" void kernel_launch(void* const* d_in, const int* in_sizes, int n_in,
                              void* d_out, int out_size)
{
    (void)in_sizes; (void)n_in; (void)out_size;
    const float* x   = (const float*)d_in[0];
    const float* lw1 = (const float*)d_in[1];
    const float* lb1 = (const float*)d_in[2];
    const float* lw2 = (const float*)d_in[3];
    const float* lb2 = (const float*)d_in[4];
    const float* lw3 = (const float*)d_in[5];
    const float* lb3 = (const float*)d_in[6];
    const float* cw1 = (const float*)d_in[7];
    const float* cb1 = (const float*)d_in[8];
    const float* cw2 = (const float*)d_in[9];
    const float* cb2 = (const float*)d_in[10];
    const float* tw1 = (const float*)d_in[11];
    const float* tb1 = (const float*)d_in[12];
    const float* tw2 = (const float*)d_in[13];
    const float* tb2 = (const float*)d_in[14];
    float* out = (float*)d_out;

    const int smB = B_SMEM_FLOATS * 4;
    const int smH = H_SMEM_FLOATS * 4;
    cudaFuncSetAttribute(local_mlp_kernel, cudaFuncAttributeMaxDynamicSharedMemorySize, smB);
    cudaFuncSetAttribute(head2_kernel,     cudaFuncAttributeMaxDynamicSharedMemorySize, smH);

    knn_part_kernel<<<dim3(NN/128, SLICES, 8), 128>>>(x);
    knn_merge_geom_kernel<<<NPTS/128, 128>>>(x, out);
    local_mlp_kernel<<<NPTS/32, 1024, smB>>>(lw1, lb1, lw2, lb2, lw3, lb3);
    head2_kernel<<<dim3(NPTS/128, 2), 1024, smH>>>(x, cw1, cb1, cw2, cb2,
                                                   tw1, tb1, tw2, tb2, out);
}

// round 14
// speedup vs baseline: 1.8692x; 1.8692x over previous
#include <cuda_runtime.h>
#include <math.h>

#define NN 4096
#define NPTS 32768
#define SLICES 4
#define SLICE_N 1024

typedef unsigned long long ull;

__device__ __forceinline__ ull pack2(float v) {
    ull r; unsigned u = __float_as_uint(v);
    asm("mov.b64 %0,{%1,%1};" : "=l"(r) : "r"(u));
    return r;
}
__device__ __forceinline__ ull pack2f(float lo, float hi) {
    ull r;
    asm("mov.b64 %0,{%1,%2};" : "=l"(r) : "r"(__float_as_uint(lo)), "r"(__float_as_uint(hi)));
    return r;
}
__device__ __forceinline__ void ffma2(ull &d, ull a, ull b) {
    asm("fma.rn.f32x2 %0, %1, %2, %0;" : "+l"(d) : "l"(a), "l"(b));
}
__device__ __forceinline__ ull mul2(ull a, ull b) {
    ull r; asm("mul.rn.f32x2 %0, %1, %2;" : "=l"(r) : "l"(a), "l"(b)); return r;
}
__device__ __forceinline__ ull add2(ull a, ull b) {
    ull r; asm("add.rn.f32x2 %0, %1, %2;" : "=l"(r) : "l"(a), "l"(b)); return r;
}
__device__ __forceinline__ ull fma2v(ull a, ull b, ull c) {
    ull r; asm("fma.rn.f32x2 %0, %1, %2, %3;" : "=l"(r) : "l"(a), "l"(b), "l"(c)); return r;
}
__device__ __forceinline__ float lo2(ull v) { return __uint_as_float((unsigned)v); }
__device__ __forceinline__ float hi2(ull v) { return __uint_as_float((unsigned)(v >> 32)); }

// scratch (static __device__, no allocation)
__device__ float g_lcc[NPTS * 10];        // (pt, k, xy)
__device__ float g_lf [NPTS * 64];        // local_feats
__device__ float g_pd [NPTS * 20];        // partial top-5 dists, 4 slices
__device__ int   g_pi [NPTS * 20];        // partial top-5 indices

// out layout: [cls 32768*128 | topo 32768*128 | angle 32768 | axes 32768*2]
#define OFF_TOPO 4194304
#define OFF_ANG  8388608
#define OFF_AX   8421376

// insert (dd, mi) into sorted-ascending register top-5 with strict < (stable by index)
#define INS5(dd, mi)                                                        \
    if (dd < d4) {                                                          \
        if (dd < d3) {                                                      \
            d4 = d3; i4 = i3;                                               \
            if (dd < d2) {                                                  \
                d3 = d2; i3 = i2;                                           \
                if (dd < d1) {                                              \
                    d2 = d1; i2 = i1;                                       \
                    if (dd < d0) { d1 = d0; i1 = i0; d0 = dd; i0 = mi; }    \
                    else          { d1 = dd; i1 = mi; }                     \
                } else { d2 = dd; i2 = mi; }                                \
            } else { d3 = dd; i3 = mi; }                                    \
        } else { d4 = dd; i4 = mi; }                                        \
    }

// ---------------- Kernel A1: partial KNN over one candidate slice (packed f32x2) ----------------
__global__ __launch_bounds__(128)
void knn_part_kernel(const float* __restrict__ xg)
{
    __shared__ ull sx[SLICE_N / 2];   // packed x pairs
    __shared__ ull sy[SLICE_N / 2];   // packed y pairs
    __shared__ ull sq[SLICE_N / 2];   // packed sq pairs

    const int b  = blockIdx.z;
    const int s  = blockIdx.y;
    const int m0 = s * SLICE_N;
    const float2* xb = reinterpret_cast<const float2*>(xg) + (size_t)b * NN;

    for (int i = threadIdx.x; i < SLICE_N / 2; i += 128) {
        float2 p0 = xb[m0 + 2*i];
        float2 p1 = xb[m0 + 2*i + 1];
        sx[i] = pack2f(p0.x, p1.x);
        sy[i] = pack2f(p0.y, p1.y);
        // sq = rn(x*x) + rn(y*y)  (jnp.sum(x*x,-1), no fma)
        float q0 = __fadd_rn(__fmul_rn(p0.x, p0.x), __fmul_rn(p0.y, p0.y));
        float q1 = __fadd_rn(__fmul_rn(p1.x, p1.x), __fmul_rn(p1.y, p1.y));
        sq[i] = pack2f(q0, q1);
    }
    __syncthreads();

    const int n = blockIdx.x * 128 + threadIdx.x;
    float2 qv = xb[n];
    const float sqn = __fadd_rn(__fmul_rn(qv.x, qv.x), __fmul_rn(qv.y, qv.y));
    const ull QX = pack2(qv.x), QY = pack2(qv.y), SQN = pack2(sqn), NEG2 = pack2(-2.0f);

    float d0 = 3.4e38f, d1 = 3.4e38f, d2 = 3.4e38f, d3 = 3.4e38f, d4 = 3.4e38f;
    int   i0 = 0, i1 = 0, i2 = 0, i3 = 0, i4 = 0;

    #pragma unroll 4
    for (int j = 0; j < SLICE_N / 2; ++j) {
        ull X = sx[j], Y = sy[j], S = sq[j];
        // dot = fma(y, qy, rn(x*qx))  (Eigen k=2 fold), dd = rn(sum - 2*dot)
        ull dot = fma2v(Y, QY, mul2(X, QX));
        ull sum = add2(SQN, S);
        ull ddp = fma2v(dot, NEG2, sum);   // exact: 2*dot has no rounding
        float ddlo = lo2(ddp), ddhi = hi2(ddp);
        int mi = m0 + 2*j;
        INS5(ddlo, mi);
        INS5(ddhi, mi + 1);
    }

    float* pd = g_pd + ((size_t)(b * NN + n)) * 20 + s * 5;
    int*   pi = g_pi + ((size_t)(b * NN + n)) * 20 + s * 5;
    pd[0] = d0; pd[1] = d1; pd[2] = d2; pd[3] = d3; pd[4] = d4;
    pi[0] = i0; pi[1] = i1; pi[2] = i2; pi[3] = i3; pi[4] = i4;
}

// ---------------- Kernel A2: merge partials + slaev2 eigh + lcc ----------------
__global__ __launch_bounds__(128)
void knn_merge_geom_kernel(const float* __restrict__ xg, float* __restrict__ out)
{
    const int pt = blockIdx.x * 128 + threadIdx.x;
    const int b  = pt >> 12;
    const int n  = pt & (NN - 1);
    const float2* xb = reinterpret_cast<const float2*>(xg) + (size_t)b * NN;

    float pd[20]; int pi[20];
    {
        const float* gp = g_pd + (size_t)pt * 20;
        const int*   gi = g_pi + (size_t)pt * 20;
        #pragma unroll
        for (int j = 0; j < 20; ++j) { pd[j] = gp[j]; pi[j] = gi[j]; }
    }

    // exact global top-5 by (d, idx) lexicographic (== lax.top_k stable order)
    int nb[5];
    unsigned used = 0;
    #pragma unroll
    for (int k = 0; k < 5; ++k) {
        float best = 3.5e38f; int bidx = 0x7fffffff; int bj = 0;
        #pragma unroll
        for (int j = 0; j < 20; ++j) {
            bool freej = !((used >> j) & 1u);
            float dj = pd[j]; int ij = pi[j];
            if (freej && (dj < best || (dj == best && ij < bidx))) {
                best = dj; bidx = ij; bj = j;
            }
        }
        used |= 1u << bj;
        nb[k] = bidx;
    }

    const float qx = xb[n].x, qy = xb[n].y;
    float rx[5], ry[5];
    #pragma unroll
    for (int k = 0; k < 5; ++k) {
        float2 p = xb[nb[k]];
        rx[k] = __fsub_rn(p.x, qx);
        ry[k] = __fsub_rn(p.y, qy);
    }
    float sxs = __fadd_rn(__fadd_rn(__fadd_rn(__fadd_rn(rx[0], rx[1]), rx[2]), rx[3]), rx[4]);
    float sys = __fadd_rn(__fadd_rn(__fadd_rn(__fadd_rn(ry[0], ry[1]), ry[2]), ry[3]), ry[4]);
    float mx = __fdiv_rn(sxs, 5.0f);
    float my = __fdiv_rn(sys, 5.0f);
    float cx[5], cy[5];
    float sxx = 0.f, sxy = 0.f, syy = 0.f;
    #pragma unroll
    for (int k = 0; k < 5; ++k) {
        cx[k] = __fsub_rn(rx[k], mx);
        cy[k] = __fsub_rn(ry[k], my);
        sxx = __fmaf_rn(cx[k], cx[k], sxx);
        sxy = __fmaf_rn(cx[k], cy[k], sxy);
        syy = __fmaf_rn(cy[k], cy[k], syy);
    }
    float a  = __fadd_rn(__fmul_rn(sxx, 0.25f), 1e-6f);
    float bv = __fmul_rn(sxy, 0.25f);
    float c  = __fadd_rn(__fmul_rn(syy, 0.25f), 1e-6f);

    // ---- LAPACK slaev2 (a,c > 0 => sm > 0 => sgn1 = +1) ----
    float smv = a + c, df = a - c;
    float adf = fabsf(df);
    float tb  = bv + bv;
    float ab  = fabsf(tb);
    float rt;
    if (adf > ab)      { float t = ab / adf; rt = adf * sqrtf(1.f + t*t); }
    else if (adf < ab) { float t = adf / ab; rt = ab * sqrtf(1.f + t*t); }
    else               { rt = ab * 1.4142135623730951f; }
    float rt1 = 0.5f * (smv + rt);
    float acmx, acmn;
    if (fabsf(a) > fabsf(c)) { acmx = a; acmn = c; } else { acmx = c; acmn = a; }
    float rt2 = (acmx / rt1) * acmn - (bv / rt1) * bv;
    float cs; int sgn2;
    if (df >= 0.f) { cs = df + rt; sgn2 = 1; }
    else           { cs = df - rt; sgn2 = -1; }
    float acs = fabsf(cs), cs1, sn1;
    if (acs > ab)       { float ct = -tb / cs; sn1 = 1.f / sqrtf(1.f + ct*ct); cs1 = ct * sn1; }
    else if (ab == 0.f) { cs1 = 1.f; sn1 = 0.f; }
    else                { float tn = -cs / tb; cs1 = 1.f / sqrtf(1.f + tn*tn); sn1 = tn * cs1; }
    if (sgn2 == 1)      { float t = cs1; cs1 = -sn1; sn1 = t; }

    float e0, e1, v00, v10, v01, v11;
    if (rt2 < rt1) { e0 = rt2; e1 = rt1; v00 = -sn1; v10 = cs1; v01 = cs1;  v11 = sn1; }
    else           { e0 = rt1; e1 = rt2; v00 = cs1;  v10 = sn1; v01 = -sn1; v11 = cs1; }

    out[OFF_ANG + pt] = atan2f(v11, v01);
    float sL = sqrtf(fmaxf(e1, 1e-6f));
    float sS = sqrtf(fmaxf(e0, 1e-6f));
    float den = fmaxf(sL, sS) + 1e-6f;
    out[OFF_AX + pt * 2 + 0] = fmaxf(sL / den, 0.2f);
    out[OFF_AX + pt * 2 + 1] = fmaxf(sS / den, 0.2f);

    float* lp = g_lcc + (size_t)pt * 10;
    #pragma unroll
    for (int k = 0; k < 5; ++k) {
        lp[2*k]   = __fmaf_rn(cy[k], v10, __fmul_rn(cx[k], v00));
        lp[2*k+1] = __fmaf_rn(cy[k], v11, __fmul_rn(cx[k], v01));
    }
}

// ---------------- Kernel B: local MLP 2->64->128->64 + max over K ----------------
// 32 points/CTA (160 rows), 512 threads. Software-pipelined k-loops.
#define B_SMEM_FLOATS (27392 + 160*133)
__global__ __launch_bounds__(512)
void local_mlp_kernel(const float* __restrict__ lw1, const float* __restrict__ lb1,
                      const float* __restrict__ lw2, const float* __restrict__ lb2,
                      const float* __restrict__ lw3, const float* __restrict__ lb3)
{
    extern __shared__ float smf[];
    float* w1s  = smf;
    float* b1s  = smf + 128;
    float* w2s  = smf + 192;
    float* b2s  = smf + 8384;
    float* w3s  = smf + 8512;
    float* b3s  = smf + 16704;
    float* lccs = smf + 16768;
    float* h1T  = smf + 17088;   // [64][161]  k-major
    float* h2s  = smf + 27392;   // [160][133]

    const int tid  = threadIdx.x;
    const int base = blockIdx.x * 32;

    for (int i = tid; i < 128;  i += 512) { w1s[i] = lw1[i]; b2s[i] = lb2[i]; }
    for (int i = tid; i < 64;   i += 512) { b1s[i] = lb1[i]; b3s[i] = lb3[i]; }
    for (int i = tid; i < 8192; i += 512) { w2s[i] = lw2[i]; w3s[i] = lw3[i]; }
    if (tid < 320) lccs[tid] = g_lcc[(size_t)base * 10 + tid];
    __syncthreads();

    // stage 1: h1 (160x64) -> h1T[c*161 + r]
    for (int idx = tid; idx < 160 * 64; idx += 512) {
        int r = idx >> 6, c = idx & 63;
        float v = fmaf(lccs[2*r], w1s[c], fmaf(lccs[2*r+1], w1s[64 + c], b1s[c]));
        h1T[c * 161 + r] = fmaxf(v, 0.f);
    }
    __syncthreads();

    const int rg = tid & 31;       // point
    const int cg = tid >> 5;       // 0..15
    const int r0 = rg * 5;

    // stage 2: h2 (160x128), tile 5 rows x 8 cols, pipelined
    {
        const int c0 = cg * 8;
        ull acc[5][4];
        ulonglong2 bp0 = *reinterpret_cast<const ulonglong2*>(b2s + c0);
        ulonglong2 bp1 = *reinterpret_cast<const ulonglong2*>(b2s + c0 + 4);
        #pragma unroll
        for (int j = 0; j < 5; ++j) {
            acc[j][0] = bp0.x; acc[j][1] = bp0.y; acc[j][2] = bp1.x; acc[j][3] = bp1.y;
        }
        ull av[5];
        #pragma unroll
        for (int j = 0; j < 5; ++j) av[j] = pack2(h1T[r0 + j]);
        ulonglong2 w0 = *reinterpret_cast<const ulonglong2*>(w2s + c0);
        ulonglong2 w1 = *reinterpret_cast<const ulonglong2*>(w2s + c0 + 4);
        for (int k = 0; k < 64; ++k) {
            // prefetch k+1 (k=63 reads h1T row 64 / w2s row 64 -> adjacent smem, unused)
            ull avn[5];
            #pragma unroll
            for (int j = 0; j < 5; ++j) avn[j] = pack2(h1T[(k + 1) * 161 + r0 + j]);
            ulonglong2 w0n = *reinterpret_cast<const ulonglong2*>(w2s + (k + 1) * 128 + c0);
            ulonglong2 w1n = *reinterpret_cast<const ulonglong2*>(w2s + (k + 1) * 128 + c0 + 4);
            #pragma unroll
            for (int j = 0; j < 5; ++j) {
                ffma2(acc[j][0], av[j], w0.x);
                ffma2(acc[j][1], av[j], w0.y);
                ffma2(acc[j][2], av[j], w1.x);
                ffma2(acc[j][3], av[j], w1.y);
            }
            #pragma unroll
            for (int j = 0; j < 5; ++j) av[j] = avn[j];
            w0 = w0n; w1 = w1n;
        }
        #pragma unroll
        for (int j = 0; j < 5; ++j) {
            float* hp = h2s + (r0 + j) * 133 + c0;
            #pragma unroll
            for (int i = 0; i < 4; ++i) {
                hp[2*i]   = fmaxf(lo2(acc[j][i]), 0.f);
                hp[2*i+1] = fmaxf(hi2(acc[j][i]), 0.f);
            }
        }
    }
    __syncthreads();

    // stage 3: h3 (160x64), tile 5 rows x 4 cols, pipelined, fused relu+max
    {
        const int c0 = cg * 4;
        ull acc3[5][2];
        ulonglong2 bp = *reinterpret_cast<const ulonglong2*>(b3s + c0);
        #pragma unroll
        for (int j = 0; j < 5; ++j) { acc3[j][0] = bp.x; acc3[j][1] = bp.y; }
        ull av[5];
        #pragma unroll
        for (int j = 0; j < 5; ++j) av[j] = pack2(h2s[(r0 + j) * 133]);
        ulonglong2 w = *reinterpret_cast<const ulonglong2*>(w3s + c0);
        for (int k = 0; k < 128; ++k) {
            ull avn[5];
            #pragma unroll
            for (int j = 0; j < 5; ++j) avn[j] = pack2(h2s[(r0 + j) * 133 + k + 1]);
            ulonglong2 wn = *reinterpret_cast<const ulonglong2*>(w3s + (k + 1) * 64 + c0);
            #pragma unroll
            for (int j = 0; j < 5; ++j) {
                ffma2(acc3[j][0], av[j], w.x);
                ffma2(acc3[j][1], av[j], w.y);
            }
            #pragma unroll
            for (int j = 0; j < 5; ++j) av[j] = avn[j];
            w = wn;
        }
        float4 o;
        float m0 = 0.f, m1 = 0.f, m2 = 0.f, m3 = 0.f;   // relu floor
        #pragma unroll
        for (int j = 0; j < 5; ++j) {
            m0 = fmaxf(m0, lo2(acc3[j][0]));
            m1 = fmaxf(m1, hi2(acc3[j][0]));
            m2 = fmaxf(m2, lo2(acc3[j][1]));
            m3 = fmaxf(m3, hi2(acc3[j][1]));
        }
        o.x = m0; o.y = m1; o.z = m2; o.w = m3;
        *reinterpret_cast<float4*>(g_lf + (size_t)(base + rg) * 64 + c0) = o;
    }
}

// ---------------- Kernel C: BOTH heads, 128 points/CTA, 512 threads ----------------
// thread tile: 2 points (p, p+64) x 16 cols; software-pipelined k-loops.
template<int INDIM>
__device__ __forceinline__ void head_body(
    const float* __restrict__ w1s, const float* __restrict__ b1s,
    const float* __restrict__ w2s, const float* __restrict__ b2s,
    const float* __restrict__ ins, float* __restrict__ hs,
    float* __restrict__ outp, int base, int tid)
{
    const int p  = tid & 63;          // points p and p+64
    const int c0 = (tid >> 6) * 16;   // warp-uniform column base

    // stage 1: 128 x 128, tile 2 rows x 16 cols, pipelined
    {
        ull acc0[8], acc1[8];
        ulonglong2 bq0 = *reinterpret_cast<const ulonglong2*>(b1s + c0);
        ulonglong2 bq1 = *reinterpret_cast<const ulonglong2*>(b1s + c0 + 4);
        ulonglong2 bq2 = *reinterpret_cast<const ulonglong2*>(b1s + c0 + 8);
        ulonglong2 bq3 = *reinterpret_cast<const ulonglong2*>(b1s + c0 + 12);
        acc0[0]=bq0.x; acc0[1]=bq0.y; acc0[2]=bq1.x; acc0[3]=bq1.y;
        acc0[4]=bq2.x; acc0[5]=bq2.y; acc0[6]=bq3.x; acc0[7]=bq3.y;
        #pragma unroll
        for (int i = 0; i < 8; ++i) acc1[i] = acc0[i];
        ull a0 = pack2(ins[p * 67]);
        ull a1 = pack2(ins[(p + 64) * 67]);
        ulonglong2 w0  = *reinterpret_cast<const ulonglong2*>(w1s + c0);
        ulonglong2 w1q = *reinterpret_cast<const ulonglong2*>(w1s + c0 + 4);
        ulonglong2 w2q = *reinterpret_cast<const ulonglong2*>(w1s + c0 + 8);
        ulonglong2 w3q = *reinterpret_cast<const ulonglong2*>(w1s + c0 + 12);
        for (int k = 0; k < INDIM; ++k) {
            // prefetch k+1 (k=INDIM-1 reads row INDIM -> adjacent smem, unused)
            ull a0n = pack2(ins[p * 67 + k + 1]);
            ull a1n = pack2(ins[(p + 64) * 67 + k + 1]);
            const float* wr = w1s + (k + 1) * 128 + c0;
            ulonglong2 w0n = *reinterpret_cast<const ulonglong2*>(wr);
            ulonglong2 w1n = *reinterpret_cast<const ulonglong2*>(wr + 4);
            ulonglong2 w2n = *reinterpret_cast<const ulonglong2*>(wr + 8);
            ulonglong2 w3n = *reinterpret_cast<const ulonglong2*>(wr + 12);
            ffma2(acc0[0], a0, w0.x);  ffma2(acc1[0], a1, w0.x);
            ffma2(acc0[1], a0, w0.y);  ffma2(acc1[1], a1, w0.y);
            ffma2(acc0[2], a0, w1q.x); ffma2(acc1[2], a1, w1q.x);
            ffma2(acc0[3], a0, w1q.y); ffma2(acc1[3], a1, w1q.y);
            ffma2(acc0[4], a0, w2q.x); ffma2(acc1[4], a1, w2q.x);
            ffma2(acc0[5], a0, w2q.y); ffma2(acc1[5], a1, w2q.y);
            ffma2(acc0[6], a0, w3q.x); ffma2(acc1[6], a1, w3q.x);
            ffma2(acc0[7], a0, w3q.y); ffma2(acc1[7], a1, w3q.y);
            a0 = a0n; a1 = a1n;
            w0 = w0n; w1q = w1n; w2q = w2n; w3q = w3n;
        }
        float* hp0 = hs + p * 131 + c0;
        float* hp1 = hs + (p + 64) * 131 + c0;
        #pragma unroll
        for (int i = 0; i < 8; ++i) {
            hp0[2*i]   = fmaxf(lo2(acc0[i]), 0.f);
            hp0[2*i+1] = fmaxf(hi2(acc0[i]), 0.f);
            hp1[2*i]   = fmaxf(lo2(acc1[i]), 0.f);
            hp1[2*i+1] = fmaxf(hi2(acc1[i]), 0.f);
        }
    }
    __syncthreads();

    // stage 2: 128 x 128, pipelined
    {
        ull acc0[8], acc1[8];
        ulonglong2 bq0 = *reinterpret_cast<const ulonglong2*>(b2s + c0);
        ulonglong2 bq1 = *reinterpret_cast<const ulonglong2*>(b2s + c0 + 4);
        ulonglong2 bq2 = *reinterpret_cast<const ulonglong2*>(b2s + c0 + 8);
        ulonglong2 bq3 = *reinterpret_cast<const ulonglong2*>(b2s + c0 + 12);
        acc0[0]=bq0.x; acc0[1]=bq0.y; acc0[2]=bq1.x; acc0[3]=bq1.y;
        acc0[4]=bq2.x; acc0[5]=bq2.y; acc0[6]=bq3.x; acc0[7]=bq3.y;
        #pragma unroll
        for (int i = 0; i < 8; ++i) acc1[i] = acc0[i];
        ull a0 = pack2(hs[p * 131]);
        ull a1 = pack2(hs[(p + 64) * 131]);
        ulonglong2 w0  = *reinterpret_cast<const ulonglong2*>(w2s + c0);
        ulonglong2 w1q = *reinterpret_cast<const ulonglong2*>(w2s + c0 + 4);
        ulonglong2 w2q = *reinterpret_cast<const ulonglong2*>(w2s + c0 + 8);
        ulonglong2 w3q = *reinterpret_cast<const ulonglong2*>(w2s + c0 + 12);
        for (int k = 0; k < 128; ++k) {
            ull a0n = pack2(hs[p * 131 + k + 1]);
            ull a1n = pack2(hs[(p + 64) * 131 + k + 1]);
            const float* wr = w2s + (k + 1) * 128 + c0;
            ulonglong2 w0n = *reinterpret_cast<const ulonglong2*>(wr);
            ulonglong2 w1n = *reinterpret_cast<const ulonglong2*>(wr + 4);
            ulonglong2 w2n = *reinterpret_cast<const ulonglong2*>(wr + 8);
            ulonglong2 w3n = *reinterpret_cast<const ulonglong2*>(wr + 12);
            ffma2(acc0[0], a0, w0.x);  ffma2(acc1[0], a1, w0.x);
            ffma2(acc0[1], a0, w0.y);  ffma2(acc1[1], a1, w0.y);
            ffma2(acc0[2], a0, w1q.x); ffma2(acc1[2], a1, w1q.x);
            ffma2(acc0[3], a0, w1q.y); ffma2(acc1[3], a1, w1q.y);
            ffma2(acc0[4], a0, w2q.x); ffma2(acc1[4], a1, w2q.x);
            ffma2(acc0[5], a0, w2q.y); ffma2(acc1[5], a1, w2q.y);
            ffma2(acc0[6], a0, w3q.x); ffma2(acc1[6], a1, w3q.x);
            ffma2(acc0[7], a0, w3q.y); ffma2(acc1[7], a1, w3q.y);
            a0 = a0n; a1 = a1n;
            w0 = w0n; w1q = w1n; w2q = w2n; w3q = w3n;
        }
        float* op0 = outp + (size_t)(base + p) * 128 + c0;
        float* op1 = outp + (size_t)(base + p + 64) * 128 + c0;
        #pragma unroll
        for (int i = 0; i < 8; ++i) {
            float2 v0 = make_float2(fmaxf(lo2(acc0[i]), 0.f), fmaxf(hi2(acc0[i]), 0.f));
            float2 v1 = make_float2(fmaxf(lo2(acc1[i]), 0.f), fmaxf(hi2(acc1[i]), 0.f));
            *reinterpret_cast<float2*>(op0 + 2*i) = v0;
            *reinterpret_cast<float2*>(op1 + 2*i) = v1;
        }
    }
}

// smem: w1s 8448 | b1s 128 | w2s 16384 | b2s 128 | ins 128*67 | hs 128*131
#define H_SMEM_FLOATS (8448 + 128 + 16384 + 128 + 128*67 + 128*131)
__global__ __launch_bounds__(512)
void head2_kernel(const float* __restrict__ xg,
                  const float* __restrict__ cw1, const float* __restrict__ cb1,
                  const float* __restrict__ cw2, const float* __restrict__ cb2,
                  const float* __restrict__ tw1, const float* __restrict__ tb1,
                  const float* __restrict__ tw2, const float* __restrict__ tb2,
                  float* __restrict__ outg)
{
    extern __shared__ float smf[];
    float* w1s = smf;
    float* b1s = smf + 8448;
    float* w2s = smf + 8576;
    float* b2s = smf + 24960;
    float* ins = smf + 25088;   // [128][67]
    float* hs  = smf + 33664;   // [128][131]

    const int head = blockIdx.y;
    const float* w1 = head ? tw1 : cw1;
    const float* b1 = head ? tb1 : cb1;
    const float* w2 = head ? tw2 : cw2;
    const float* b2 = head ? tb2 : cb2;
    const int indim = head ? 64 : 66;
    const int xoff  = head ? 0 : 2;
    float* outp = outg + (head ? OFF_TOPO : 0);

    const int tid  = threadIdx.x;
    const int base = blockIdx.x * 128;

    for (int i = tid; i < indim * 128; i += 512) w1s[i] = w1[i];
    for (int i = tid; i < 16384;       i += 512) w2s[i] = w2[i];
    if (tid < 128) { b1s[tid] = b1[tid]; b2s[tid] = b2[tid]; }
    for (int idx = tid; idx < 128 * 64; idx += 512) {
        int p = idx >> 6, c = idx & 63;
        ins[p * 67 + xoff + c] = g_lf[(size_t)(base + p) * 64 + c];
    }
    if (!head && tid < 256) {
        int p = tid >> 1, c = tid & 1;
        ins[p * 67 + c] = xg[(size_t)(base + p) * 2 + c];
    }
    __syncthreads();

    if (head) head_body<64>(w1s, b1s, w2s, b2s, ins, hs, outp, base, tid);
    else      head_body<66>(w1s, b1s, w2s, b2s, ins, hs, outp, base, tid);
}

// ---------------- launch ----------------
extern "C" void kernel_launch(void* const* d_in, const int* in_sizes, int n_in,
                              void* d_out, int out_size)
{
    (void)in_sizes; (void)n_in; (void)out_size;
    const float* x   = (const float*)d_in[0];
    const float* lw1 = (const float*)d_in[1];
    const float* lb1 = (const float*)d_in[2];
    const float* lw2 = (const float*)d_in[3];
    const float* lb2 = (const float*)d_in[4];
    const float* lw3 = (const float*)d_in[5];
    const float* lb3 = (const float*)d_in[6];
    const float* cw1 = (const float*)d_in[7];
    const float* cb1 = (const float*)d_in[8];
    const float* cw2 = (const float*)d_in[9];
    const float* cb2 = (const float*)d_in[10];
    const float* tw1 = (const float*)d_in[11];
    const float* tb1 = (const float*)d_in[12];
    const float* tw2 = (const float*)d_in[13];
    const float* tb2 = (const float*)d_in[14];
    float* out = (float*)d_out;

    const int smB = B_SMEM_FLOATS * 4;
    const int smH = H_SMEM_FLOATS * 4;
    cudaFuncSetAttribute(local_mlp_kernel, cudaFuncAttributeMaxDynamicSharedMemorySize, smB);
    cudaFuncSetAttribute(head2_kernel,     cudaFuncAttributeMaxDynamicSharedMemorySize, smH);

    knn_part_kernel<<<dim3(NN/128, SLICES, 8), 128>>>(x);
    knn_merge_geom_kernel<<<NPTS/128, 128>>>(x, out);
    local_mlp_kernel<<<NPTS/32, 512, smB>>>(lw1, lb1, lw2, lb2, lw3, lb3);
    head2_kernel<<<dim3(NPTS/128, 2), 512, smH>>>(x, cw1, cb1, cw2, cb2,
                                                  tw1, tb1, tw2, tb2, out);
}

// round 15
// speedup vs baseline: 1.8887x; 1.0104x over previous
#include <cuda_runtime.h>
#include <math.h>

#define NN 4096
#define NPTS 32768
#define SLICES 4
#define SLICE_N 1024

typedef unsigned long long ull;

__device__ __forceinline__ ull pack2(float v) {
    ull r; unsigned u = __float_as_uint(v);
    asm("mov.b64 %0,{%1,%1};" : "=l"(r) : "r"(u));
    return r;
}
__device__ __forceinline__ ull pack2f(float lo, float hi) {
    ull r;
    asm("mov.b64 %0,{%1,%2};" : "=l"(r) : "r"(__float_as_uint(lo)), "r"(__float_as_uint(hi)));
    return r;
}
__device__ __forceinline__ void ffma2(ull &d, ull a, ull b) {
    asm("fma.rn.f32x2 %0, %1, %2, %0;" : "+l"(d) : "l"(a), "l"(b));
}
__device__ __forceinline__ ull mul2(ull a, ull b) {
    ull r; asm("mul.rn.f32x2 %0, %1, %2;" : "=l"(r) : "l"(a), "l"(b)); return r;
}
__device__ __forceinline__ ull add2(ull a, ull b) {
    ull r; asm("add.rn.f32x2 %0, %1, %2;" : "=l"(r) : "l"(a), "l"(b)); return r;
}
__device__ __forceinline__ ull fma2v(ull a, ull b, ull c) {
    ull r; asm("fma.rn.f32x2 %0, %1, %2, %3;" : "=l"(r) : "l"(a), "l"(b), "l"(c)); return r;
}
__device__ __forceinline__ float lo2(ull v) { return __uint_as_float((unsigned)v); }
__device__ __forceinline__ float hi2(ull v) { return __uint_as_float((unsigned)(v >> 32)); }

// scratch (static __device__, no allocation)
__device__ float g_lcc[NPTS * 10];        // (pt, k, xy)
__device__ float g_lf [NPTS * 64];        // local_feats
__device__ float g_pd [NPTS * 20];        // partial top-5 dists, 4 slices
__device__ int   g_pi [NPTS * 20];        // partial top-5 indices

// out layout: [cls 32768*128 | topo 32768*128 | angle 32768 | axes 32768*2]
#define OFF_TOPO 4194304
#define OFF_ANG  8388608
#define OFF_AX   8421376

// insert (dd, mi) into sorted-ascending register top-5 with strict < (stable by index)
#define INS5(dd, mi)                                                        \
    if (dd < d4) {                                                          \
        if (dd < d3) {                                                      \
            d4 = d3; i4 = i3;                                               \
            if (dd < d2) {                                                  \
                d3 = d2; i3 = i2;                                           \
                if (dd < d1) {                                              \
                    d2 = d1; i2 = i1;                                       \
                    if (dd < d0) { d1 = d0; i1 = i0; d0 = dd; i0 = mi; }    \
                    else          { d1 = dd; i1 = mi; }                     \
                } else { d2 = dd; i2 = mi; }                                \
            } else { d3 = dd; i3 = mi; }                                    \
        } else { d4 = dd; i4 = mi; }                                        \
    }

// ---------------- Kernel A1: partial KNN over one candidate slice (packed f32x2) ----------------
__global__ __launch_bounds__(128)
void knn_part_kernel(const float* __restrict__ xg)
{
    __shared__ ull sx[SLICE_N / 2];   // packed x pairs
    __shared__ ull sy[SLICE_N / 2];   // packed y pairs
    __shared__ ull sq[SLICE_N / 2];   // packed sq pairs

    const int b  = blockIdx.z;
    const int s  = blockIdx.y;
    const int m0 = s * SLICE_N;
    const float2* xb = reinterpret_cast<const float2*>(xg) + (size_t)b * NN;

    for (int i = threadIdx.x; i < SLICE_N / 2; i += 128) {
        float2 p0 = xb[m0 + 2*i];
        float2 p1 = xb[m0 + 2*i + 1];
        sx[i] = pack2f(p0.x, p1.x);
        sy[i] = pack2f(p0.y, p1.y);
        // sq = rn(x*x) + rn(y*y)  (jnp.sum(x*x,-1), no fma)
        float q0 = __fadd_rn(__fmul_rn(p0.x, p0.x), __fmul_rn(p0.y, p0.y));
        float q1 = __fadd_rn(__fmul_rn(p1.x, p1.x), __fmul_rn(p1.y, p1.y));
        sq[i] = pack2f(q0, q1);
    }
    __syncthreads();

    const int n = blockIdx.x * 128 + threadIdx.x;
    float2 qv = xb[n];
    const float sqn = __fadd_rn(__fmul_rn(qv.x, qv.x), __fmul_rn(qv.y, qv.y));
    const ull QX = pack2(qv.x), QY = pack2(qv.y), SQN = pack2(sqn), NEG2 = pack2(-2.0f);

    float d0 = 3.4e38f, d1 = 3.4e38f, d2 = 3.4e38f, d3 = 3.4e38f, d4 = 3.4e38f;
    int   i0 = 0, i1 = 0, i2 = 0, i3 = 0, i4 = 0;

    #pragma unroll 8
    for (int j = 0; j < SLICE_N / 2; ++j) {
        ull X = sx[j], Y = sy[j], S = sq[j];
        // dot = fma(y, qy, rn(x*qx))  (Eigen k=2 fold), dd = rn(sum - 2*dot)
        ull dot = fma2v(Y, QY, mul2(X, QX));
        ull sum = add2(SQN, S);
        ull ddp = fma2v(dot, NEG2, sum);   // exact: 2*dot has no rounding
        float ddlo = lo2(ddp), ddhi = hi2(ddp);
        int mi = m0 + 2*j;
        INS5(ddlo, mi);
        INS5(ddhi, mi + 1);
    }

    float* pd = g_pd + ((size_t)(b * NN + n)) * 20 + s * 5;
    int*   pi = g_pi + ((size_t)(b * NN + n)) * 20 + s * 5;
    pd[0] = d0; pd[1] = d1; pd[2] = d2; pd[3] = d3; pd[4] = d4;
    pi[0] = i0; pi[1] = i1; pi[2] = i2; pi[3] = i3; pi[4] = i4;
}

// ---------------- Kernel A2: merge partials + slaev2 eigh + lcc ----------------
__global__ __launch_bounds__(128)
void knn_merge_geom_kernel(const float* __restrict__ xg, float* __restrict__ out)
{
    const int pt = blockIdx.x * 128 + threadIdx.x;
    const int b  = pt >> 12;
    const int n  = pt & (NN - 1);
    const float2* xb = reinterpret_cast<const float2*>(xg) + (size_t)b * NN;

    float pd[20]; int pi[20];
    {
        const float* gp = g_pd + (size_t)pt * 20;
        const int*   gi = g_pi + (size_t)pt * 20;
        #pragma unroll
        for (int j = 0; j < 20; ++j) { pd[j] = gp[j]; pi[j] = gi[j]; }
    }

    // exact global top-5 by (d, idx) lexicographic (== lax.top_k stable order)
    int nb[5];
    unsigned used = 0;
    #pragma unroll
    for (int k = 0; k < 5; ++k) {
        float best = 3.5e38f; int bidx = 0x7fffffff; int bj = 0;
        #pragma unroll
        for (int j = 0; j < 20; ++j) {
            bool freej = !((used >> j) & 1u);
            float dj = pd[j]; int ij = pi[j];
            if (freej && (dj < best || (dj == best && ij < bidx))) {
                best = dj; bidx = ij; bj = j;
            }
        }
        used |= 1u << bj;
        nb[k] = bidx;
    }

    const float qx = xb[n].x, qy = xb[n].y;
    float rx[5], ry[5];
    #pragma unroll
    for (int k = 0; k < 5; ++k) {
        float2 p = xb[nb[k]];
        rx[k] = __fsub_rn(p.x, qx);
        ry[k] = __fsub_rn(p.y, qy);
    }
    float sxs = __fadd_rn(__fadd_rn(__fadd_rn(__fadd_rn(rx[0], rx[1]), rx[2]), rx[3]), rx[4]);
    float sys = __fadd_rn(__fadd_rn(__fadd_rn(__fadd_rn(ry[0], ry[1]), ry[2]), ry[3]), ry[4]);
    float mx = __fdiv_rn(sxs, 5.0f);
    float my = __fdiv_rn(sys, 5.0f);
    float cx[5], cy[5];
    float sxx = 0.f, sxy = 0.f, syy = 0.f;
    #pragma unroll
    for (int k = 0; k < 5; ++k) {
        cx[k] = __fsub_rn(rx[k], mx);
        cy[k] = __fsub_rn(ry[k], my);
        sxx = __fmaf_rn(cx[k], cx[k], sxx);
        sxy = __fmaf_rn(cx[k], cy[k], sxy);
        syy = __fmaf_rn(cy[k], cy[k], syy);
    }
    float a  = __fadd_rn(__fmul_rn(sxx, 0.25f), 1e-6f);
    float bv = __fmul_rn(sxy, 0.25f);
    float c  = __fadd_rn(__fmul_rn(syy, 0.25f), 1e-6f);

    // ---- LAPACK slaev2 (a,c > 0 => sm > 0 => sgn1 = +1) ----
    float smv = a + c, df = a - c;
    float adf = fabsf(df);
    float tb  = bv + bv;
    float ab  = fabsf(tb);
    float rt;
    if (adf > ab)      { float t = ab / adf; rt = adf * sqrtf(1.f + t*t); }
    else if (adf < ab) { float t = adf / ab; rt = ab * sqrtf(1.f + t*t); }
    else               { rt = ab * 1.4142135623730951f; }
    float rt1 = 0.5f * (smv + rt);
    float acmx, acmn;
    if (fabsf(a) > fabsf(c)) { acmx = a; acmn = c; } else { acmx = c; acmn = a; }
    float rt2 = (acmx / rt1) * acmn - (bv / rt1) * bv;
    float cs; int sgn2;
    if (df >= 0.f) { cs = df + rt; sgn2 = 1; }
    else           { cs = df - rt; sgn2 = -1; }
    float acs = fabsf(cs), cs1, sn1;
    if (acs > ab)       { float ct = -tb / cs; sn1 = 1.f / sqrtf(1.f + ct*ct); cs1 = ct * sn1; }
    else if (ab == 0.f) { cs1 = 1.f; sn1 = 0.f; }
    else                { float tn = -cs / tb; cs1 = 1.f / sqrtf(1.f + tn*tn); sn1 = tn * cs1; }
    if (sgn2 == 1)      { float t = cs1; cs1 = -sn1; sn1 = t; }

    float e0, e1, v00, v10, v01, v11;
    if (rt2 < rt1) { e0 = rt2; e1 = rt1; v00 = -sn1; v10 = cs1; v01 = cs1;  v11 = sn1; }
    else           { e0 = rt1; e1 = rt2; v00 = cs1;  v10 = sn1; v01 = -sn1; v11 = cs1; }

    out[OFF_ANG + pt] = atan2f(v11, v01);
    float sL = sqrtf(fmaxf(e1, 1e-6f));
    float sS = sqrtf(fmaxf(e0, 1e-6f));
    float den = fmaxf(sL, sS) + 1e-6f;
    out[OFF_AX + pt * 2 + 0] = fmaxf(sL / den, 0.2f);
    out[OFF_AX + pt * 2 + 1] = fmaxf(sS / den, 0.2f);

    float* lp = g_lcc + (size_t)pt * 10;
    #pragma unroll
    for (int k = 0; k < 5; ++k) {
        lp[2*k]   = __fmaf_rn(cy[k], v10, __fmul_rn(cx[k], v00));
        lp[2*k+1] = __fmaf_rn(cy[k], v11, __fmul_rn(cx[k], v01));
    }
}

// ---------------- Kernel B: local MLP 2->64->128->64 + max over K ----------------
// 32 points/CTA (160 rows), 512 threads. Ping-pong pipelined k-loops (no MOVs).
#define B_SMEM_FLOATS (27392 + 160*133)
__global__ __launch_bounds__(512)
void local_mlp_kernel(const float* __restrict__ lw1, const float* __restrict__ lb1,
                      const float* __restrict__ lw2, const float* __restrict__ lb2,
                      const float* __restrict__ lw3, const float* __restrict__ lb3)
{
    extern __shared__ float smf[];
    float* w1s  = smf;
    float* b1s  = smf + 128;
    float* w2s  = smf + 192;
    float* b2s  = smf + 8384;
    float* w3s  = smf + 8512;
    float* b3s  = smf + 16704;
    float* lccs = smf + 16768;
    float* h1T  = smf + 17088;   // [64][161]  k-major
    float* h2s  = smf + 27392;   // [160][133]

    const int tid  = threadIdx.x;
    const int base = blockIdx.x * 32;

    for (int i = tid; i < 128;  i += 512) { w1s[i] = lw1[i]; b2s[i] = lb2[i]; }
    for (int i = tid; i < 64;   i += 512) { b1s[i] = lb1[i]; b3s[i] = lb3[i]; }
    for (int i = tid; i < 8192; i += 512) { w2s[i] = lw2[i]; w3s[i] = lw3[i]; }
    if (tid < 320) lccs[tid] = g_lcc[(size_t)base * 10 + tid];
    __syncthreads();

    // stage 1: h1 (160x64) -> h1T[c*161 + r]
    for (int idx = tid; idx < 160 * 64; idx += 512) {
        int r = idx >> 6, c = idx & 63;
        float v = fmaf(lccs[2*r], w1s[c], fmaf(lccs[2*r+1], w1s[64 + c], b1s[c]));
        h1T[c * 161 + r] = fmaxf(v, 0.f);
    }
    __syncthreads();

    const int rg = tid & 31;       // point
    const int cg = tid >> 5;       // 0..15
    const int r0 = rg * 5;

    // stage 2: h2 (160x128), tile 5 rows x 8 cols, ping-pong pipelined
    {
        const int c0 = cg * 8;
        ull acc[5][4];
        ulonglong2 bp0 = *reinterpret_cast<const ulonglong2*>(b2s + c0);
        ulonglong2 bp1 = *reinterpret_cast<const ulonglong2*>(b2s + c0 + 4);
        #pragma unroll
        for (int j = 0; j < 5; ++j) {
            acc[j][0] = bp0.x; acc[j][1] = bp0.y; acc[j][2] = bp1.x; acc[j][3] = bp1.y;
        }
        ull avA[5], avB[5];
        ulonglong2 w0A, w1A, w0B, w1B;
        #pragma unroll
        for (int j = 0; j < 5; ++j) avA[j] = pack2(h1T[r0 + j]);
        w0A = *reinterpret_cast<const ulonglong2*>(w2s + c0);
        w1A = *reinterpret_cast<const ulonglong2*>(w2s + c0 + 4);
        for (int k = 0; k < 64; k += 2) {
            // prefetch k+1 -> B
            #pragma unroll
            for (int j = 0; j < 5; ++j) avB[j] = pack2(h1T[(k + 1) * 161 + r0 + j]);
            w0B = *reinterpret_cast<const ulonglong2*>(w2s + (k + 1) * 128 + c0);
            w1B = *reinterpret_cast<const ulonglong2*>(w2s + (k + 1) * 128 + c0 + 4);
            // compute k with A
            #pragma unroll
            for (int j = 0; j < 5; ++j) {
                ffma2(acc[j][0], avA[j], w0A.x);
                ffma2(acc[j][1], avA[j], w0A.y);
                ffma2(acc[j][2], avA[j], w1A.x);
                ffma2(acc[j][3], avA[j], w1A.y);
            }
            // prefetch k+2 -> A (k=62: row 64 -> adjacent smem, unused)
            #pragma unroll
            for (int j = 0; j < 5; ++j) avA[j] = pack2(h1T[(k + 2) * 161 + r0 + j]);
            w0A = *reinterpret_cast<const ulonglong2*>(w2s + (k + 2) * 128 + c0);
            w1A = *reinterpret_cast<const ulonglong2*>(w2s + (k + 2) * 128 + c0 + 4);
            // compute k+1 with B
            #pragma unroll
            for (int j = 0; j < 5; ++j) {
                ffma2(acc[j][0], avB[j], w0B.x);
                ffma2(acc[j][1], avB[j], w0B.y);
                ffma2(acc[j][2], avB[j], w1B.x);
                ffma2(acc[j][3], avB[j], w1B.y);
            }
        }
        #pragma unroll
        for (int j = 0; j < 5; ++j) {
            float* hp = h2s + (r0 + j) * 133 + c0;
            #pragma unroll
            for (int i = 0; i < 4; ++i) {
                hp[2*i]   = fmaxf(lo2(acc[j][i]), 0.f);
                hp[2*i+1] = fmaxf(hi2(acc[j][i]), 0.f);
            }
        }
    }
    __syncthreads();

    // stage 3: h3 (160x64), tile 5 rows x 4 cols, ping-pong, fused relu+max
    {
        const int c0 = cg * 4;
        ull acc3[5][2];
        ulonglong2 bp = *reinterpret_cast<const ulonglong2*>(b3s + c0);
        #pragma unroll
        for (int j = 0; j < 5; ++j) { acc3[j][0] = bp.x; acc3[j][1] = bp.y; }
        ull avA[5], avB[5];
        ulonglong2 wA, wB;
        #pragma unroll
        for (int j = 0; j < 5; ++j) avA[j] = pack2(h2s[(r0 + j) * 133]);
        wA = *reinterpret_cast<const ulonglong2*>(w3s + c0);
        for (int k = 0; k < 128; k += 2) {
            #pragma unroll
            for (int j = 0; j < 5; ++j) avB[j] = pack2(h2s[(r0 + j) * 133 + k + 1]);
            wB = *reinterpret_cast<const ulonglong2*>(w3s + (k + 1) * 64 + c0);
            #pragma unroll
            for (int j = 0; j < 5; ++j) {
                ffma2(acc3[j][0], avA[j], wA.x);
                ffma2(acc3[j][1], avA[j], wA.y);
            }
            #pragma unroll
            for (int j = 0; j < 5; ++j) avA[j] = pack2(h2s[(r0 + j) * 133 + k + 2]);
            wA = *reinterpret_cast<const ulonglong2*>(w3s + (k + 2) * 64 + c0);
            #pragma unroll
            for (int j = 0; j < 5; ++j) {
                ffma2(acc3[j][0], avB[j], wB.x);
                ffma2(acc3[j][1], avB[j], wB.y);
            }
        }
        float4 o;
        float m0 = 0.f, m1 = 0.f, m2 = 0.f, m3 = 0.f;   // relu floor
        #pragma unroll
        for (int j = 0; j < 5; ++j) {
            m0 = fmaxf(m0, lo2(acc3[j][0]));
            m1 = fmaxf(m1, hi2(acc3[j][0]));
            m2 = fmaxf(m2, lo2(acc3[j][1]));
            m3 = fmaxf(m3, hi2(acc3[j][1]));
        }
        o.x = m0; o.y = m1; o.z = m2; o.w = m3;
        *reinterpret_cast<float4*>(g_lf + (size_t)(base + rg) * 64 + c0) = o;
    }
}

// ---------------- Kernel C: BOTH heads, 128 points/CTA, 512 threads ----------------
// thread tile: 2 points (p, p+64) x 16 cols; ping-pong pipelined.
#define HEAD_FMA16(A0, A1, W0, W1, W2, W3)                          \
    ffma2(acc0[0], A0, W0.x);  ffma2(acc1[0], A1, W0.x);            \
    ffma2(acc0[1], A0, W0.y);  ffma2(acc1[1], A1, W0.y);            \
    ffma2(acc0[2], A0, W1.x);  ffma2(acc1[2], A1, W1.x);            \
    ffma2(acc0[3], A0, W1.y);  ffma2(acc1[3], A1, W1.y);            \
    ffma2(acc0[4], A0, W2.x);  ffma2(acc1[4], A1, W2.x);            \
    ffma2(acc0[5], A0, W2.y);  ffma2(acc1[5], A1, W2.y);            \
    ffma2(acc0[6], A0, W3.x);  ffma2(acc1[6], A1, W3.x);            \
    ffma2(acc0[7], A0, W3.y);  ffma2(acc1[7], A1, W3.y);

template<int INDIM>
__device__ __forceinline__ void head_body(
    const float* __restrict__ w1s, const float* __restrict__ b1s,
    const float* __restrict__ w2s, const float* __restrict__ b2s,
    const float* __restrict__ ins, float* __restrict__ hs,
    float* __restrict__ outp, int base, int tid)
{
    const int p  = tid & 63;          // points p and p+64
    const int c0 = (tid >> 6) * 16;   // warp-uniform column base

    // stage 1: 128 x INDIM -> 128, ping-pong pipelined
    {
        ull acc0[8], acc1[8];
        ulonglong2 bq0 = *reinterpret_cast<const ulonglong2*>(b1s + c0);
        ulonglong2 bq1 = *reinterpret_cast<const ulonglong2*>(b1s + c0 + 4);
        ulonglong2 bq2 = *reinterpret_cast<const ulonglong2*>(b1s + c0 + 8);
        ulonglong2 bq3 = *reinterpret_cast<const ulonglong2*>(b1s + c0 + 12);
        acc0[0]=bq0.x; acc0[1]=bq0.y; acc0[2]=bq1.x; acc0[3]=bq1.y;
        acc0[4]=bq2.x; acc0[5]=bq2.y; acc0[6]=bq3.x; acc0[7]=bq3.y;
        #pragma unroll
        for (int i = 0; i < 8; ++i) acc1[i] = acc0[i];
        ull a0A = pack2(ins[p * 67]);
        ull a1A = pack2(ins[(p + 64) * 67]);
        ulonglong2 w0A = *reinterpret_cast<const ulonglong2*>(w1s + c0);
        ulonglong2 w1A = *reinterpret_cast<const ulonglong2*>(w1s + c0 + 4);
        ulonglong2 w2A = *reinterpret_cast<const ulonglong2*>(w1s + c0 + 8);
        ulonglong2 w3A = *reinterpret_cast<const ulonglong2*>(w1s + c0 + 12);
        ull a0B, a1B; ulonglong2 w0B, w1B, w2B, w3B;
        for (int k = 0; k < INDIM; k += 2) {
            // prefetch k+1 -> B
            a0B = pack2(ins[p * 67 + k + 1]);
            a1B = pack2(ins[(p + 64) * 67 + k + 1]);
            const float* wrB = w1s + (k + 1) * 128 + c0;
            w0B = *reinterpret_cast<const ulonglong2*>(wrB);
            w1B = *reinterpret_cast<const ulonglong2*>(wrB + 4);
            w2B = *reinterpret_cast<const ulonglong2*>(wrB + 8);
            w3B = *reinterpret_cast<const ulonglong2*>(wrB + 12);
            HEAD_FMA16(a0A, a1A, w0A, w1A, w2A, w3A)
            // prefetch k+2 -> A (last: row INDIM -> adjacent smem, unused)
            a0A = pack2(ins[p * 67 + k + 2]);
            a1A = pack2(ins[(p + 64) * 67 + k + 2]);
            const float* wrA = w1s + (k + 2) * 128 + c0;
            w0A = *reinterpret_cast<const ulonglong2*>(wrA);
            w1A = *reinterpret_cast<const ulonglong2*>(wrA + 4);
            w2A = *reinterpret_cast<const ulonglong2*>(wrA + 8);
            w3A = *reinterpret_cast<const ulonglong2*>(wrA + 12);
            HEAD_FMA16(a0B, a1B, w0B, w1B, w2B, w3B)
        }
        float* hp0 = hs + p * 131 + c0;
        float* hp1 = hs + (p + 64) * 131 + c0;
        #pragma unroll
        for (int i = 0; i < 8; ++i) {
            hp0[2*i]   = fmaxf(lo2(acc0[i]), 0.f);
            hp0[2*i+1] = fmaxf(hi2(acc0[i]), 0.f);
            hp1[2*i]   = fmaxf(lo2(acc1[i]), 0.f);
            hp1[2*i+1] = fmaxf(hi2(acc1[i]), 0.f);
        }
    }
    __syncthreads();

    // stage 2: 128 x 128 -> 128, ping-pong pipelined
    {
        ull acc0[8], acc1[8];
        ulonglong2 bq0 = *reinterpret_cast<const ulonglong2*>(b2s + c0);
        ulonglong2 bq1 = *reinterpret_cast<const ulonglong2*>(b2s + c0 + 4);
        ulonglong2 bq2 = *reinterpret_cast<const ulonglong2*>(b2s + c0 + 8);
        ulonglong2 bq3 = *reinterpret_cast<const ulonglong2*>(b2s + c0 + 12);
        acc0[0]=bq0.x; acc0[1]=bq0.y; acc0[2]=bq1.x; acc0[3]=bq1.y;
        acc0[4]=bq2.x; acc0[5]=bq2.y; acc0[6]=bq3.x; acc0[7]=bq3.y;
        #pragma unroll
        for (int i = 0; i < 8; ++i) acc1[i] = acc0[i];
        ull a0A = pack2(hs[p * 131]);
        ull a1A = pack2(hs[(p + 64) * 131]);
        ulonglong2 w0A = *reinterpret_cast<const ulonglong2*>(w2s + c0);
        ulonglong2 w1A = *reinterpret_cast<const ulonglong2*>(w2s + c0 + 4);
        ulonglong2 w2A = *reinterpret_cast<const ulonglong2*>(w2s + c0 + 8);
        ulonglong2 w3A = *reinterpret_cast<const ulonglong2*>(w2s + c0 + 12);
        ull a0B, a1B; ulonglong2 w0B, w1B, w2B, w3B;
        for (int k = 0; k < 128; k += 2) {
            a0B = pack2(hs[p * 131 + k + 1]);
            a1B = pack2(hs[(p + 64) * 131 + k + 1]);
            const float* wrB = w2s + (k + 1) * 128 + c0;
            w0B = *reinterpret_cast<const ulonglong2*>(wrB);
            w1B = *reinterpret_cast<const ulonglong2*>(wrB + 4);
            w2B = *reinterpret_cast<const ulonglong2*>(wrB + 8);
            w3B = *reinterpret_cast<const ulonglong2*>(wrB + 12);
            HEAD_FMA16(a0A, a1A, w0A, w1A, w2A, w3A)
            a0A = pack2(hs[p * 131 + k + 2]);
            a1A = pack2(hs[(p + 64) * 131 + k + 2]);
            const float* wrA = w2s + (k + 2) * 128 + c0;
            w0A = *reinterpret_cast<const ulonglong2*>(wrA);
            w1A = *reinterpret_cast<const ulonglong2*>(wrA + 4);
            w2A = *reinterpret_cast<const ulonglong2*>(wrA + 8);
            w3A = *reinterpret_cast<const ulonglong2*>(wrA + 12);
            HEAD_FMA16(a0B, a1B, w0B, w1B, w2B, w3B)
        }
        float* op0 = outp + (size_t)(base + p) * 128 + c0;
        float* op1 = outp + (size_t)(base + p + 64) * 128 + c0;
        #pragma unroll
        for (int i = 0; i < 8; ++i) {
            float2 v0 = make_float2(fmaxf(lo2(acc0[i]), 0.f), fmaxf(hi2(acc0[i]), 0.f));
            float2 v1 = make_float2(fmaxf(lo2(acc1[i]), 0.f), fmaxf(hi2(acc1[i]), 0.f));
            *reinterpret_cast<float2*>(op0 + 2*i) = v0;
            *reinterpret_cast<float2*>(op1 + 2*i) = v1;
        }
    }
}

// smem: w1s 8448 | b1s 128 | w2s 16384 | b2s 128 | ins 128*67 | hs 128*131
#define H_SMEM_FLOATS (8448 + 128 + 16384 + 128 + 128*67 + 128*131)
__global__ __launch_bounds__(512)
void head2_kernel(const float* __restrict__ xg,
                  const float* __restrict__ cw1, const float* __restrict__ cb1,
                  const float* __restrict__ cw2, const float* __restrict__ cb2,
                  const float* __restrict__ tw1, const float* __restrict__ tb1,
                  const float* __restrict__ tw2, const float* __restrict__ tb2,
                  float* __restrict__ outg)
{
    extern __shared__ float smf[];
    float* w1s = smf;
    float* b1s = smf + 8448;
    float* w2s = smf + 8576;
    float* b2s = smf + 24960;
    float* ins = smf + 25088;   // [128][67]
    float* hs  = smf + 33664;   // [128][131]

    const int head = blockIdx.y;
    const float* w1 = head ? tw1 : cw1;
    const float* b1 = head ? tb1 : cb1;
    const float* w2 = head ? tw2 : cw2;
    const float* b2 = head ? tb2 : cb2;
    const int indim = head ? 64 : 66;
    const int xoff  = head ? 0 : 2;
    float* outp = outg + (head ? OFF_TOPO : 0);

    const int tid  = threadIdx.x;
    const int base = blockIdx.x * 128;

    for (int i = tid; i < indim * 128; i += 512) w1s[i] = w1[i];
    for (int i = tid; i < 16384;       i += 512) w2s[i] = w2[i];
    if (tid < 128) { b1s[tid] = b1[tid]; b2s[tid] = b2[tid]; }
    for (int idx = tid; idx < 128 * 64; idx += 512) {
        int p = idx >> 6, c = idx & 63;
        ins[p * 67 + xoff + c] = g_lf[(size_t)(base + p) * 64 + c];
    }
    if (!head && tid < 256) {
        int p = tid >> 1, c = tid & 1;
        ins[p * 67 + c] = xg[(size_t)(base + p) * 2 + c];
    }
    __syncthreads();

    if (head) head_body<64>(w1s, b1s, w2s, b2s, ins, hs, outp, base, tid);
    else      head_body<66>(w1s, b1s, w2s, b2s, ins, hs, outp, base, tid);
}

// ---------------- launch ----------------
extern "C" void kernel_launch(void* const* d_in, const int* in_sizes, int n_in,
                              void* d_out, int out_size)
{
    (void)in_sizes; (void)n_in; (void)out_size;
    const float* x   = (const float*)d_in[0];
    const float* lw1 = (const float*)d_in[1];
    const float* lb1 = (const float*)d_in[2];
    const float* lw2 = (const float*)d_in[3];
    const float* lb2 = (const float*)d_in[4];
    const float* lw3 = (const float*)d_in[5];
    const float* lb3 = (const float*)d_in[6];
    const float* cw1 = (const float*)d_in[7];
    const float* cb1 = (const float*)d_in[8];
    const float* cw2 = (const float*)d_in[9];
    const float* cb2 = (const float*)d_in[10];
    const float* tw1 = (const float*)d_in[11];
    const float* tb1 = (const float*)d_in[12];
    const float* tw2 = (const float*)d_in[13];
    const float* tb2 = (const float*)d_in[14];
    float* out = (float*)d_out;

    const int smB = B_SMEM_FLOATS * 4;
    const int smH = H_SMEM_FLOATS * 4;
    cudaFuncSetAttribute(local_mlp_kernel, cudaFuncAttributeMaxDynamicSharedMemorySize, smB);
    cudaFuncSetAttribute(head2_kernel,     cudaFuncAttributeMaxDynamicSharedMemorySize, smH);

    knn_part_kernel<<<dim3(NN/128, SLICES, 8), 128>>>(x);
    knn_merge_geom_kernel<<<NPTS/128, 128>>>(x, out);
    local_mlp_kernel<<<NPTS/32, 512, smB>>>(lw1, lb1, lw2, lb2, lw3, lb3);
    head2_kernel<<<dim3(NPTS/128, 2), 512, smH>>>(x, cw1, cb1, cw2, cb2,
                                                  tw1, tb1, tw2, tb2, out);
}

// round 16
// speedup vs baseline: 2.0902x; 1.1067x over previous
#include <cuda_runtime.h>
#include <math.h>

#define NN 4096
#define NPTS 32768
#define SLICES 4
#define SLICE_N 1024

typedef unsigned long long ull;

__device__ __forceinline__ ull pack2(float v) {
    ull r; unsigned u = __float_as_uint(v);
    asm("mov.b64 %0,{%1,%1};" : "=l"(r) : "r"(u));
    return r;
}
__device__ __forceinline__ ull pack2f(float lo, float hi) {
    ull r;
    asm("mov.b64 %0,{%1,%2};" : "=l"(r) : "r"(__float_as_uint(lo)), "r"(__float_as_uint(hi)));
    return r;
}
__device__ __forceinline__ void ffma2(ull &d, ull a, ull b) {
    asm("fma.rn.f32x2 %0, %1, %2, %0;" : "+l"(d) : "l"(a), "l"(b));
}
__device__ __forceinline__ ull mul2(ull a, ull b) {
    ull r; asm("mul.rn.f32x2 %0, %1, %2;" : "=l"(r) : "l"(a), "l"(b)); return r;
}
__device__ __forceinline__ ull add2(ull a, ull b) {
    ull r; asm("add.rn.f32x2 %0, %1, %2;" : "=l"(r) : "l"(a), "l"(b)); return r;
}
__device__ __forceinline__ ull fma2v(ull a, ull b, ull c) {
    ull r; asm("fma.rn.f32x2 %0, %1, %2, %3;" : "=l"(r) : "l"(a), "l"(b), "l"(c)); return r;
}
__device__ __forceinline__ float lo2(ull v) { return __uint_as_float((unsigned)v); }
__device__ __forceinline__ float hi2(ull v) { return __uint_as_float((unsigned)(v >> 32)); }

// scratch (static __device__, no allocation)
__device__ float g_lcc[NPTS * 10];        // (pt, k, xy)
__device__ float g_lf [NPTS * 64];        // local_feats
__device__ float g_pd [NPTS * 20];        // partial top-5 dists, 4 slices
__device__ int   g_pi [NPTS * 20];        // partial top-5 indices

// out layout: [cls 32768*128 | topo 32768*128 | angle 32768 | axes 32768*2]
#define OFF_TOPO 4194304
#define OFF_ANG  8388608
#define OFF_AX   8421376

// flat insert: single guard branch, straight-line predicated shift inside.
// Semantics identical to the nested strict-< sorted insert (stable tie by index).
#define INS5F(dd, mi)                                                       \
    if (dd < d4) {                                                          \
        bool p3 = dd < d3, p2 = dd < d2, p1 = dd < d1, p0 = dd < d0;        \
        d4 = p3 ? d3 : dd;            i4 = p3 ? i3 : mi;                    \
        d3 = p3 ? (p2 ? d2 : dd) : d3; i3 = p3 ? (p2 ? i2 : mi) : i3;       \
        d2 = p2 ? (p1 ? d1 : dd) : d2; i2 = p2 ? (p1 ? i1 : mi) : i2;       \
        d1 = p1 ? (p0 ? d0 : dd) : d1; i1 = p1 ? (p0 ? i0 : mi) : i1;       \
        d0 = p0 ? dd : d0;            i0 = p0 ? mi : i0;                    \
    }

// ---------------- Kernel A1: partial KNN over one candidate slice (packed f32x2) ----------------
__global__ __launch_bounds__(128)
void knn_part_kernel(const float* __restrict__ xg)
{
    __shared__ ulonglong2 sxy[SLICE_N / 2];  // packed {x-pair, y-pair}
    __shared__ ull        sq [SLICE_N / 2];  // packed sq pairs

    const int b  = blockIdx.z;
    const int s  = blockIdx.y;
    const int m0 = s * SLICE_N;
    const float2* xb = reinterpret_cast<const float2*>(xg) + (size_t)b * NN;

    for (int i = threadIdx.x; i < SLICE_N / 2; i += 128) {
        float2 p0 = xb[m0 + 2*i];
        float2 p1 = xb[m0 + 2*i + 1];
        ulonglong2 v;
        v.x = pack2f(p0.x, p1.x);
        v.y = pack2f(p0.y, p1.y);
        sxy[i] = v;
        // sq = rn(x*x) + rn(y*y)  (jnp.sum(x*x,-1), no fma)
        float q0 = __fadd_rn(__fmul_rn(p0.x, p0.x), __fmul_rn(p0.y, p0.y));
        float q1 = __fadd_rn(__fmul_rn(p1.x, p1.x), __fmul_rn(p1.y, p1.y));
        sq[i] = pack2f(q0, q1);
    }
    __syncthreads();

    const int n = blockIdx.x * 128 + threadIdx.x;
    float2 qv = xb[n];
    const float sqn = __fadd_rn(__fmul_rn(qv.x, qv.x), __fmul_rn(qv.y, qv.y));
    const ull QX = pack2(qv.x), QY = pack2(qv.y), SQN = pack2(sqn), NEG2 = pack2(-2.0f);

    float d0 = 3.4e38f, d1 = 3.4e38f, d2 = 3.4e38f, d3 = 3.4e38f, d4 = 3.4e38f;
    int   i0 = 0, i1 = 0, i2 = 0, i3 = 0, i4 = 0;

    #pragma unroll 8
    for (int j = 0; j < SLICE_N / 2; ++j) {
        ulonglong2 XY = sxy[j];
        ull S = sq[j];
        // dot = fma(y, qy, rn(x*qx))  (Eigen k=2 fold), dd = rn(sum - 2*dot)
        ull dot = fma2v(XY.y, QY, mul2(XY.x, QX));
        ull sum = add2(SQN, S);
        ull ddp = fma2v(dot, NEG2, sum);   // exact: 2*dot has no rounding
        float ddlo = lo2(ddp), ddhi = hi2(ddp);
        int mi = m0 + 2*j;
        INS5F(ddlo, mi);
        INS5F(ddhi, (mi + 1));
    }

    float* pd = g_pd + ((size_t)(b * NN + n)) * 20 + s * 5;
    int*   pi = g_pi + ((size_t)(b * NN + n)) * 20 + s * 5;
    pd[0] = d0; pd[1] = d1; pd[2] = d2; pd[3] = d3; pd[4] = d4;
    pi[0] = i0; pi[1] = i1; pi[2] = i2; pi[3] = i3; pi[4] = i4;
}

// ---------------- Kernel A2: merge partials + slaev2 eigh + lcc ----------------
__global__ __launch_bounds__(128)
void knn_merge_geom_kernel(const float* __restrict__ xg, float* __restrict__ out)
{
    const int pt = blockIdx.x * 128 + threadIdx.x;
    const int b  = pt >> 12;
    const int n  = pt & (NN - 1);
    const float2* xb = reinterpret_cast<const float2*>(xg) + (size_t)b * NN;

    float pd[20]; int pi[20];
    {
        const float* gp = g_pd + (size_t)pt * 20;
        const int*   gi = g_pi + (size_t)pt * 20;
        #pragma unroll
        for (int j = 0; j < 20; ++j) { pd[j] = gp[j]; pi[j] = gi[j]; }
    }

    // exact global top-5 by (d, idx) lexicographic (== lax.top_k stable order)
    int nb[5];
    unsigned used = 0;
    #pragma unroll
    for (int k = 0; k < 5; ++k) {
        float best = 3.5e38f; int bidx = 0x7fffffff; int bj = 0;
        #pragma unroll
        for (int j = 0; j < 20; ++j) {
            bool freej = !((used >> j) & 1u);
            float dj = pd[j]; int ij = pi[j];
            if (freej && (dj < best || (dj == best && ij < bidx))) {
                best = dj; bidx = ij; bj = j;
            }
        }
        used |= 1u << bj;
        nb[k] = bidx;
    }

    const float qx = xb[n].x, qy = xb[n].y;
    float rx[5], ry[5];
    #pragma unroll
    for (int k = 0; k < 5; ++k) {
        float2 p = xb[nb[k]];
        rx[k] = __fsub_rn(p.x, qx);
        ry[k] = __fsub_rn(p.y, qy);
    }
    float sxs = __fadd_rn(__fadd_rn(__fadd_rn(__fadd_rn(rx[0], rx[1]), rx[2]), rx[3]), rx[4]);
    float sys = __fadd_rn(__fadd_rn(__fadd_rn(__fadd_rn(ry[0], ry[1]), ry[2]), ry[3]), ry[4]);
    float mx = __fdiv_rn(sxs, 5.0f);
    float my = __fdiv_rn(sys, 5.0f);
    float cx[5], cy[5];
    float sxx = 0.f, sxy = 0.f, syy = 0.f;
    #pragma unroll
    for (int k = 0; k < 5; ++k) {
        cx[k] = __fsub_rn(rx[k], mx);
        cy[k] = __fsub_rn(ry[k], my);
        sxx = __fmaf_rn(cx[k], cx[k], sxx);
        sxy = __fmaf_rn(cx[k], cy[k], sxy);
        syy = __fmaf_rn(cy[k], cy[k], syy);
    }
    float a  = __fadd_rn(__fmul_rn(sxx, 0.25f), 1e-6f);
    float bv = __fmul_rn(sxy, 0.25f);
    float c  = __fadd_rn(__fmul_rn(syy, 0.25f), 1e-6f);

    // ---- LAPACK slaev2 (a,c > 0 => sm > 0 => sgn1 = +1) ----
    float smv = a + c, df = a - c;
    float adf = fabsf(df);
    float tb  = bv + bv;
    float ab  = fabsf(tb);
    float rt;
    if (adf > ab)      { float t = ab / adf; rt = adf * sqrtf(1.f + t*t); }
    else if (adf < ab) { float t = adf / ab; rt = ab * sqrtf(1.f + t*t); }
    else               { rt = ab * 1.4142135623730951f; }
    float rt1 = 0.5f * (smv + rt);
    float acmx, acmn;
    if (fabsf(a) > fabsf(c)) { acmx = a; acmn = c; } else { acmx = c; acmn = a; }
    float rt2 = (acmx / rt1) * acmn - (bv / rt1) * bv;
    float cs; int sgn2;
    if (df >= 0.f) { cs = df + rt; sgn2 = 1; }
    else           { cs = df - rt; sgn2 = -1; }
    float acs = fabsf(cs), cs1, sn1;
    if (acs > ab)       { float ct = -tb / cs; sn1 = 1.f / sqrtf(1.f + ct*ct); cs1 = ct * sn1; }
    else if (ab == 0.f) { cs1 = 1.f; sn1 = 0.f; }
    else                { float tn = -cs / tb; cs1 = 1.f / sqrtf(1.f + tn*tn); sn1 = tn * cs1; }
    if (sgn2 == 1)      { float t = cs1; cs1 = -sn1; sn1 = t; }

    float e0, e1, v00, v10, v01, v11;
    if (rt2 < rt1) { e0 = rt2; e1 = rt1; v00 = -sn1; v10 = cs1; v01 = cs1;  v11 = sn1; }
    else           { e0 = rt1; e1 = rt2; v00 = cs1;  v10 = sn1; v01 = -sn1; v11 = cs1; }

    out[OFF_ANG + pt] = atan2f(v11, v01);
    float sL = sqrtf(fmaxf(e1, 1e-6f));
    float sS = sqrtf(fmaxf(e0, 1e-6f));
    float den = fmaxf(sL, sS) + 1e-6f;
    out[OFF_AX + pt * 2 + 0] = fmaxf(sL / den, 0.2f);
    out[OFF_AX + pt * 2 + 1] = fmaxf(sS / den, 0.2f);

    float* lp = g_lcc + (size_t)pt * 10;
    #pragma unroll
    for (int k = 0; k < 5; ++k) {
        lp[2*k]   = __fmaf_rn(cy[k], v10, __fmul_rn(cx[k], v00));
        lp[2*k+1] = __fmaf_rn(cy[k], v11, __fmul_rn(cx[k], v01));
    }
}

// ---------------- Kernel B: local MLP 2->64->128->64 + max over K ----------------
// 32 points/CTA (160 rows), 512 threads. Ping-pong pipelined k-loops (no MOVs).
#define B_SMEM_FLOATS (27392 + 160*133)
__global__ __launch_bounds__(512)
void local_mlp_kernel(const float* __restrict__ lw1, const float* __restrict__ lb1,
                      const float* __restrict__ lw2, const float* __restrict__ lb2,
                      const float* __restrict__ lw3, const float* __restrict__ lb3)
{
    extern __shared__ float smf[];
    float* w1s  = smf;
    float* b1s  = smf + 128;
    float* w2s  = smf + 192;
    float* b2s  = smf + 8384;
    float* w3s  = smf + 8512;
    float* b3s  = smf + 16704;
    float* lccs = smf + 16768;
    float* h1T  = smf + 17088;   // [64][161]  k-major
    float* h2s  = smf + 27392;   // [160][133]

    const int tid  = threadIdx.x;
    const int base = blockIdx.x * 32;

    for (int i = tid; i < 128;  i += 512) { w1s[i] = lw1[i]; b2s[i] = lb2[i]; }
    for (int i = tid; i < 64;   i += 512) { b1s[i] = lb1[i]; b3s[i] = lb3[i]; }
    for (int i = tid; i < 8192; i += 512) { w2s[i] = lw2[i]; w3s[i] = lw3[i]; }
    if (tid < 320) lccs[tid] = g_lcc[(size_t)base * 10 + tid];
    __syncthreads();

    // stage 1: h1 (160x64) -> h1T[c*161 + r]
    for (int idx = tid; idx < 160 * 64; idx += 512) {
        int r = idx >> 6, c = idx & 63;
        float v = fmaf(lccs[2*r], w1s[c], fmaf(lccs[2*r+1], w1s[64 + c], b1s[c]));
        h1T[c * 161 + r] = fmaxf(v, 0.f);
    }
    __syncthreads();

    const int rg = tid & 31;       // point
    const int cg = tid >> 5;       // 0..15
    const int r0 = rg * 5;

    // stage 2: h2 (160x128), tile 5 rows x 8 cols, ping-pong pipelined
    {
        const int c0 = cg * 8;
        ull acc[5][4];
        ulonglong2 bp0 = *reinterpret_cast<const ulonglong2*>(b2s + c0);
        ulonglong2 bp1 = *reinterpret_cast<const ulonglong2*>(b2s + c0 + 4);
        #pragma unroll
        for (int j = 0; j < 5; ++j) {
            acc[j][0] = bp0.x; acc[j][1] = bp0.y; acc[j][2] = bp1.x; acc[j][3] = bp1.y;
        }
        ull avA[5], avB[5];
        ulonglong2 w0A, w1A, w0B, w1B;
        #pragma unroll
        for (int j = 0; j < 5; ++j) avA[j] = pack2(h1T[r0 + j]);
        w0A = *reinterpret_cast<const ulonglong2*>(w2s + c0);
        w1A = *reinterpret_cast<const ulonglong2*>(w2s + c0 + 4);
        for (int k = 0; k < 64; k += 2) {
            // prefetch k+1 -> B
            #pragma unroll
            for (int j = 0; j < 5; ++j) avB[j] = pack2(h1T[(k + 1) * 161 + r0 + j]);
            w0B = *reinterpret_cast<const ulonglong2*>(w2s + (k + 1) * 128 + c0);
            w1B = *reinterpret_cast<const ulonglong2*>(w2s + (k + 1) * 128 + c0 + 4);
            // compute k with A
            #pragma unroll
            for (int j = 0; j < 5; ++j) {
                ffma2(acc[j][0], avA[j], w0A.x);
                ffma2(acc[j][1], avA[j], w0A.y);
                ffma2(acc[j][2], avA[j], w1A.x);
                ffma2(acc[j][3], avA[j], w1A.y);
            }
            // prefetch k+2 -> A (k=62: row 64 -> adjacent smem, unused)
            #pragma unroll
            for (int j = 0; j < 5; ++j) avA[j] = pack2(h1T[(k + 2) * 161 + r0 + j]);
            w0A = *reinterpret_cast<const ulonglong2*>(w2s + (k + 2) * 128 + c0);
            w1A = *reinterpret_cast<const ulonglong2*>(w2s + (k + 2) * 128 + c0 + 4);
            // compute k+1 with B
            #pragma unroll
            for (int j = 0; j < 5; ++j) {
                ffma2(acc[j][0], avB[j], w0B.x);
                ffma2(acc[j][1], avB[j], w0B.y);
                ffma2(acc[j][2], avB[j], w1B.x);
                ffma2(acc[j][3], avB[j], w1B.y);
            }
        }
        #pragma unroll
        for (int j = 0; j < 5; ++j) {
            float* hp = h2s + (r0 + j) * 133 + c0;
            #pragma unroll
            for (int i = 0; i < 4; ++i) {
                hp[2*i]   = fmaxf(lo2(acc[j][i]), 0.f);
                hp[2*i+1] = fmaxf(hi2(acc[j][i]), 0.f);
            }
        }
    }
    __syncthreads();

    // stage 3: h3 (160x64), tile 5 rows x 4 cols, ping-pong, fused relu+max
    {
        const int c0 = cg * 4;
        ull acc3[5][2];
        ulonglong2 bp = *reinterpret_cast<const ulonglong2*>(b3s + c0);
        #pragma unroll
        for (int j = 0; j < 5; ++j) { acc3[j][0] = bp.x; acc3[j][1] = bp.y; }
        ull avA[5], avB[5];
        ulonglong2 wA, wB;
        #pragma unroll
        for (int j = 0; j < 5; ++j) avA[j] = pack2(h2s[(r0 + j) * 133]);
        wA = *reinterpret_cast<const ulonglong2*>(w3s + c0);
        for (int k = 0; k < 128; k += 2) {
            #pragma unroll
            for (int j = 0; j < 5; ++j) avB[j] = pack2(h2s[(r0 + j) * 133 + k + 1]);
            wB = *reinterpret_cast<const ulonglong2*>(w3s + (k + 1) * 64 + c0);
            #pragma unroll
            for (int j = 0; j < 5; ++j) {
                ffma2(acc3[j][0], avA[j], wA.x);
                ffma2(acc3[j][1], avA[j], wA.y);
            }
            #pragma unroll
            for (int j = 0; j < 5; ++j) avA[j] = pack2(h2s[(r0 + j) * 133 + k + 2]);
            wA = *reinterpret_cast<const ulonglong2*>(w3s + (k + 2) * 64 + c0);
            #pragma unroll
            for (int j = 0; j < 5; ++j) {
                ffma2(acc3[j][0], avB[j], wB.x);
                ffma2(acc3[j][1], avB[j], wB.y);
            }
        }
        float4 o;
        float m0 = 0.f, m1 = 0.f, m2 = 0.f, m3 = 0.f;   // relu floor
        #pragma unroll
        for (int j = 0; j < 5; ++j) {
            m0 = fmaxf(m0, lo2(acc3[j][0]));
            m1 = fmaxf(m1, hi2(acc3[j][0]));
            m2 = fmaxf(m2, lo2(acc3[j][1]));
            m3 = fmaxf(m3, hi2(acc3[j][1]));
        }
        o.x = m0; o.y = m1; o.z = m2; o.w = m3;
        *reinterpret_cast<float4*>(g_lf + (size_t)(base + rg) * 64 + c0) = o;
    }
}

// ---------------- Kernel C: BOTH heads, 128 points/CTA, 512 threads ----------------
// thread tile: 2 points (p, p+64) x 16 cols; ping-pong pipelined.
#define HEAD_FMA16(A0, A1, W0, W1, W2, W3)                          \
    ffma2(acc0[0], A0, W0.x);  ffma2(acc1[0], A1, W0.x);            \
    ffma2(acc0[1], A0, W0.y);  ffma2(acc1[1], A1, W0.y);            \
    ffma2(acc0[2], A0, W1.x);  ffma2(acc1[2], A1, W1.x);            \
    ffma2(acc0[3], A0, W1.y);  ffma2(acc1[3], A1, W1.y);            \
    ffma2(acc0[4], A0, W2.x);  ffma2(acc1[4], A1, W2.x);            \
    ffma2(acc0[5], A0, W2.y);  ffma2(acc1[5], A1, W2.y);            \
    ffma2(acc0[6], A0, W3.x);  ffma2(acc1[6], A1, W3.x);            \
    ffma2(acc0[7], A0, W3.y);  ffma2(acc1[7], A1, W3.y);

template<int INDIM>
__device__ __forceinline__ void head_body(
    const float* __restrict__ w1s, const float* __restrict__ b1s,
    const float* __restrict__ w2s, const float* __restrict__ b2s,
    const float* __restrict__ ins, float* __restrict__ hs,
    float* __restrict__ outp, int base, int tid)
{
    const int p  = tid & 63;          // points p and p+64
    const int c0 = (tid >> 6) * 16;   // warp-uniform column base

    // stage 1: 128 x INDIM -> 128, ping-pong pipelined
    {
        ull acc0[8], acc1[8];
        ulonglong2 bq0 = *reinterpret_cast<const ulonglong2*>(b1s + c0);
        ulonglong2 bq1 = *reinterpret_cast<const ulonglong2*>(b1s + c0 + 4);
        ulonglong2 bq2 = *reinterpret_cast<const ulonglong2*>(b1s + c0 + 8);
        ulonglong2 bq3 = *reinterpret_cast<const ulonglong2*>(b1s + c0 + 12);
        acc0[0]=bq0.x; acc0[1]=bq0.y; acc0[2]=bq1.x; acc0[3]=bq1.y;
        acc0[4]=bq2.x; acc0[5]=bq2.y; acc0[6]=bq3.x; acc0[7]=bq3.y;
        #pragma unroll
        for (int i = 0; i < 8; ++i) acc1[i] = acc0[i];
        ull a0A = pack2(ins[p * 67]);
        ull a1A = pack2(ins[(p + 64) * 67]);
        ulonglong2 w0A = *reinterpret_cast<const ulonglong2*>(w1s + c0);
        ulonglong2 w1A = *reinterpret_cast<const ulonglong2*>(w1s + c0 + 4);
        ulonglong2 w2A = *reinterpret_cast<const ulonglong2*>(w1s + c0 + 8);
        ulonglong2 w3A = *reinterpret_cast<const ulonglong2*>(w1s + c0 + 12);
        ull a0B, a1B; ulonglong2 w0B, w1B, w2B, w3B;
        for (int k = 0; k < INDIM; k += 2) {
            // prefetch k+1 -> B
            a0B = pack2(ins[p * 67 + k + 1]);
            a1B = pack2(ins[(p + 64) * 67 + k + 1]);
            const float* wrB = w1s + (k + 1) * 128 + c0;
            w0B = *reinterpret_cast<const ulonglong2*>(wrB);
            w1B = *reinterpret_cast<const ulonglong2*>(wrB + 4);
            w2B = *reinterpret_cast<const ulonglong2*>(wrB + 8);
            w3B = *reinterpret_cast<const ulonglong2*>(wrB + 12);
            HEAD_FMA16(a0A, a1A, w0A, w1A, w2A, w3A)
            // prefetch k+2 -> A (last: row INDIM -> adjacent smem, unused)
            a0A = pack2(ins[p * 67 + k + 2]);
            a1A = pack2(ins[(p + 64) * 67 + k + 2]);
            const float* wrA = w1s + (k + 2) * 128 + c0;
            w0A = *reinterpret_cast<const ulonglong2*>(wrA);
            w1A = *reinterpret_cast<const ulonglong2*>(wrA + 4);
            w2A = *reinterpret_cast<const ulonglong2*>(wrA + 8);
            w3A = *reinterpret_cast<const ulonglong2*>(wrA + 12);
            HEAD_FMA16(a0B, a1B, w0B, w1B, w2B, w3B)
        }
        float* hp0 = hs + p * 131 + c0;
        float* hp1 = hs + (p + 64) * 131 + c0;
        #pragma unroll
        for (int i = 0; i < 8; ++i) {
            hp0[2*i]   = fmaxf(lo2(acc0[i]), 0.f);
            hp0[2*i+1] = fmaxf(hi2(acc0[i]), 0.f);
            hp1[2*i]   = fmaxf(lo2(acc1[i]), 0.f);
            hp1[2*i+1] = fmaxf(hi2(acc1[i]), 0.f);
        }
    }
    __syncthreads();

    // stage 2: 128 x 128 -> 128, ping-pong pipelined
    {
        ull acc0[8], acc1[8];
        ulonglong2 bq0 = *reinterpret_cast<const ulonglong2*>(b2s + c0);
        ulonglong2 bq1 = *reinterpret_cast<const ulonglong2*>(b2s + c0 + 4);
        ulonglong2 bq2 = *reinterpret_cast<const ulonglong2*>(b2s + c0 + 8);
        ulonglong2 bq3 = *reinterpret_cast<const ulonglong2*>(b2s + c0 + 12);
        acc0[0]=bq0.x; acc0[1]=bq0.y; acc0[2]=bq1.x; acc0[3]=bq1.y;
        acc0[4]=bq2.x; acc0[5]=bq2.y; acc0[6]=bq3.x; acc0[7]=bq3.y;
        #pragma unroll
        for (int i = 0; i < 8; ++i) acc1[i] = acc0[i];
        ull a0A = pack2(hs[p * 131]);
        ull a1A = pack2(hs[(p + 64) * 131]);
        ulonglong2 w0A = *reinterpret_cast<const ulonglong2*>(w2s + c0);
        ulonglong2 w1A = *reinterpret_cast<const ulonglong2*>(w2s + c0 + 4);
        ulonglong2 w2A = *reinterpret_cast<const ulonglong2*>(w2s + c0 + 8);
        ulonglong2 w3A = *reinterpret_cast<const ulonglong2*>(w2s + c0 + 12);
        ull a0B, a1B; ulonglong2 w0B, w1B, w2B, w3B;
        for (int k = 0; k < 128; k += 2) {
            a0B = pack2(hs[p * 131 + k + 1]);
            a1B = pack2(hs[(p + 64) * 131 + k + 1]);
            const float* wrB = w2s + (k + 1) * 128 + c0;
            w0B = *reinterpret_cast<const ulonglong2*>(wrB);
            w1B = *reinterpret_cast<const ulonglong2*>(wrB + 4);
            w2B = *reinterpret_cast<const ulonglong2*>(wrB + 8);
            w3B = *reinterpret_cast<const ulonglong2*>(wrB + 12);
            HEAD_FMA16(a0A, a1A, w0A, w1A, w2A, w3A)
            a0A = pack2(hs[p * 131 + k + 2]);
            a1A = pack2(hs[(p + 64) * 131 + k + 2]);
            const float* wrA = w2s + (k + 2) * 128 + c0;
            w0A = *reinterpret_cast<const ulonglong2*>(wrA);
            w1A = *reinterpret_cast<const ulonglong2*>(wrA + 4);
            w2A = *reinterpret_cast<const ulonglong2*>(wrA + 8);
            w3A = *reinterpret_cast<const ulonglong2*>(wrA + 12);
            HEAD_FMA16(a0B, a1B, w0B, w1B, w2B, w3B)
        }
        float* op0 = outp + (size_t)(base + p) * 128 + c0;
        float* op1 = outp + (size_t)(base + p + 64) * 128 + c0;
        #pragma unroll
        for (int i = 0; i < 8; ++i) {
            float2 v0 = make_float2(fmaxf(lo2(acc0[i]), 0.f), fmaxf(hi2(acc0[i]), 0.f));
            float2 v1 = make_float2(fmaxf(lo2(acc1[i]), 0.f), fmaxf(hi2(acc1[i]), 0.f));
            *reinterpret_cast<float2*>(op0 + 2*i) = v0;
            *reinterpret_cast<float2*>(op1 + 2*i) = v1;
        }
    }
}

// smem: w1s 8448 | b1s 128 | w2s 16384 | b2s 128 | ins 128*67 | hs 128*131
#define H_SMEM_FLOATS (8448 + 128 + 16384 + 128 + 128*67 + 128*131)
__global__ __launch_bounds__(512)
void head2_kernel(const float* __restrict__ xg,
                  const float* __restrict__ cw1, const float* __restrict__ cb1,
                  const float* __restrict__ cw2, const float* __restrict__ cb2,
                  const float* __restrict__ tw1, const float* __restrict__ tb1,
                  const float* __restrict__ tw2, const float* __restrict__ tb2,
                  float* __restrict__ outg)
{
    extern __shared__ float smf[];
    float* w1s = smf;
    float* b1s = smf + 8448;
    float* w2s = smf + 8576;
    float* b2s = smf + 24960;
    float* ins = smf + 25088;   // [128][67]
    float* hs  = smf + 33664;   // [128][131]

    const int head = blockIdx.y;
    const float* w1 = head ? tw1 : cw1;
    const float* b1 = head ? tb1 : cb1;
    const float* w2 = head ? tw2 : cw2;
    const float* b2 = head ? tb2 : cb2;
    const int indim = head ? 64 : 66;
    const int xoff  = head ? 0 : 2;
    float* outp = outg + (head ? OFF_TOPO : 0);

    const int tid  = threadIdx.x;
    const int base = blockIdx.x * 128;

    for (int i = tid; i < indim * 128; i += 512) w1s[i] = w1[i];
    for (int i = tid; i < 16384;       i += 512) w2s[i] = w2[i];
    if (tid < 128) { b1s[tid] = b1[tid]; b2s[tid] = b2[tid]; }
    for (int idx = tid; idx < 128 * 64; idx += 512) {
        int p = idx >> 6, c = idx & 63;
        ins[p * 67 + xoff + c] = g_lf[(size_t)(base + p) * 64 + c];
    }
    if (!head && tid < 256) {
        int p = tid >> 1, c = tid & 1;
        ins[p * 67 + c] = xg[(size_t)(base + p) * 2 + c];
    }
    __syncthreads();

    if (head) head_body<64>(w1s, b1s, w2s, b2s, ins, hs, outp, base, tid);
    else      head_body<66>(w1s, b1s, w2s, b2s, ins, hs, outp, base, tid);
}

// ---------------- launch ----------------
extern "C" void kernel_launch(void* const* d_in, const int* in_sizes, int n_in,
                              void* d_out, int out_size)
{
    (void)in_sizes; (void)n_in; (void)out_size;
    const float* x   = (const float*)d_in[0];
    const float* lw1 = (const float*)d_in[1];
    const float* lb1 = (const float*)d_in[2];
    const float* lw2 = (const float*)d_in[3];
    const float* lb2 = (const float*)d_in[4];
    const float* lw3 = (const float*)d_in[5];
    const float* lb3 = (const float*)d_in[6];
    const float* cw1 = (const float*)d_in[7];
    const float* cb1 = (const float*)d_in[8];
    const float* cw2 = (const float*)d_in[9];
    const float* cb2 = (const float*)d_in[10];
    const float* tw1 = (const float*)d_in[11];
    const float* tb1 = (const float*)d_in[12];
    const float* tw2 = (const float*)d_in[13];
    const float* tb2 = (const float*)d_in[14];
    float* out = (float*)d_out;

    const int smB = B_SMEM_FLOATS * 4;
    const int smH = H_SMEM_FLOATS * 4;
    cudaFuncSetAttribute(local_mlp_kernel, cudaFuncAttributeMaxDynamicSharedMemorySize, smB);
    cudaFuncSetAttribute(head2_kernel,     cudaFuncAttributeMaxDynamicSharedMemorySize, smH);

    knn_part_kernel<<<dim3(NN/128, SLICES, 8), 128>>>(x);
    knn_merge_geom_kernel<<<NPTS/128, 128>>>(x, out);
    local_mlp_kernel<<<NPTS/32, 512, smB>>>(lw1, lb1, lw2, lb2, lw3, lb3);
    head2_kernel<<<dim3(NPTS/128, 2), 512, smH>>>(x, cw1, cb1, cw2, cb2,
                                                  tw1, tb1, tw2, tb2, out);
}

// round 17
// speedup vs baseline: 2.1166x; 1.0126x over previous
#include <cuda_runtime.h>
#include <math.h>

#define NN 4096
#define NPTS 32768
#define SLICES 4
#define SLICE_N 1024

typedef unsigned long long ull;

__device__ __forceinline__ ull pack2(float v) {
    ull r; unsigned u = __float_as_uint(v);
    asm("mov.b64 %0,{%1,%1};" : "=l"(r) : "r"(u));
    return r;
}
__device__ __forceinline__ ull pack2f(float lo, float hi) {
    ull r;
    asm("mov.b64 %0,{%1,%2};" : "=l"(r) : "r"(__float_as_uint(lo)), "r"(__float_as_uint(hi)));
    return r;
}
__device__ __forceinline__ void ffma2(ull &d, ull a, ull b) {
    asm("fma.rn.f32x2 %0, %1, %2, %0;" : "+l"(d) : "l"(a), "l"(b));
}
__device__ __forceinline__ ull mul2(ull a, ull b) {
    ull r; asm("mul.rn.f32x2 %0, %1, %2;" : "=l"(r) : "l"(a), "l"(b)); return r;
}
__device__ __forceinline__ ull add2(ull a, ull b) {
    ull r; asm("add.rn.f32x2 %0, %1, %2;" : "=l"(r) : "l"(a), "l"(b)); return r;
}
__device__ __forceinline__ ull fma2v(ull a, ull b, ull c) {
    ull r; asm("fma.rn.f32x2 %0, %1, %2, %3;" : "=l"(r) : "l"(a), "l"(b), "l"(c)); return r;
}
__device__ __forceinline__ float lo2(ull v) { return __uint_as_float((unsigned)v); }
__device__ __forceinline__ float hi2(ull v) { return __uint_as_float((unsigned)(v >> 32)); }

// scratch (static __device__, no allocation)
__device__ float g_lcc[NPTS * 10];        // (pt, k, xy)
__device__ float g_lf [NPTS * 64];        // local_feats
__device__ float g_pd [NPTS * 20];        // partial top-5 dists, 4 slices
__device__ int   g_pi [NPTS * 20];        // partial top-5 indices

// out layout: [cls 32768*128 | topo 32768*128 | angle 32768 | axes 32768*2]
#define OFF_TOPO 4194304
#define OFF_ANG  8388608
#define OFF_AX   8421376

// flat insert: single guard branch, straight-line predicated shift inside.
#define INS5F(dd, mi)                                                       \
    if (dd < d4) {                                                          \
        bool p3 = dd < d3, p2 = dd < d2, p1 = dd < d1, p0 = dd < d0;        \
        d4 = p3 ? d3 : dd;            i4 = p3 ? i3 : mi;                    \
        d3 = p3 ? (p2 ? d2 : dd) : d3; i3 = p3 ? (p2 ? i2 : mi) : i3;       \
        d2 = p2 ? (p1 ? d1 : dd) : d2; i2 = p2 ? (p1 ? i1 : mi) : i2;       \
        d1 = p1 ? (p0 ? d0 : dd) : d1; i1 = p1 ? (p0 ? i0 : mi) : i1;       \
        d0 = p0 ? dd : d0;            i0 = p0 ? mi : i0;                    \
    }

// ---------------- Kernel A1: partial KNN over one candidate slice (packed f32x2) ----------------
__global__ __launch_bounds__(128)
void knn_part_kernel(const float* __restrict__ xg)
{
    __shared__ ulonglong2 sxy[SLICE_N / 2];  // packed {x-pair, y-pair}
    __shared__ ull        sq [SLICE_N / 2];  // packed sq pairs

    const int b  = blockIdx.z;
    const int s  = blockIdx.y;
    const int m0 = s * SLICE_N;
    const float2* xb = reinterpret_cast<const float2*>(xg) + (size_t)b * NN;

    for (int i = threadIdx.x; i < SLICE_N / 2; i += 128) {
        float2 p0 = xb[m0 + 2*i];
        float2 p1 = xb[m0 + 2*i + 1];
        ulonglong2 v;
        v.x = pack2f(p0.x, p1.x);
        v.y = pack2f(p0.y, p1.y);
        sxy[i] = v;
        float q0 = __fadd_rn(__fmul_rn(p0.x, p0.x), __fmul_rn(p0.y, p0.y));
        float q1 = __fadd_rn(__fmul_rn(p1.x, p1.x), __fmul_rn(p1.y, p1.y));
        sq[i] = pack2f(q0, q1);
    }
    __syncthreads();

    const int n = blockIdx.x * 128 + threadIdx.x;
    float2 qv = xb[n];
    const float sqn = __fadd_rn(__fmul_rn(qv.x, qv.x), __fmul_rn(qv.y, qv.y));
    const ull QX = pack2(qv.x), QY = pack2(qv.y), SQN = pack2(sqn), NEG2 = pack2(-2.0f);

    float d0 = 3.4e38f, d1 = 3.4e38f, d2 = 3.4e38f, d3 = 3.4e38f, d4 = 3.4e38f;
    int   i0 = 0, i1 = 0, i2 = 0, i3 = 0, i4 = 0;

    #pragma unroll 8
    for (int j = 0; j < SLICE_N / 2; ++j) {
        ulonglong2 XY = sxy[j];
        ull S = sq[j];
        ull dot = fma2v(XY.y, QY, mul2(XY.x, QX));
        ull sum = add2(SQN, S);
        ull ddp = fma2v(dot, NEG2, sum);   // exact: 2*dot has no rounding
        float ddlo = lo2(ddp), ddhi = hi2(ddp);
        int mi = m0 + 2*j;
        INS5F(ddlo, mi);
        INS5F(ddhi, (mi + 1));
    }

    float* pd = g_pd + ((size_t)(b * NN + n)) * 20 + s * 5;
    int*   pi = g_pi + ((size_t)(b * NN + n)) * 20 + s * 5;
    pd[0] = d0; pd[1] = d1; pd[2] = d2; pd[3] = d3; pd[4] = d4;
    pi[0] = i0; pi[1] = i1; pi[2] = i2; pi[3] = i3; pi[4] = i4;
}

// ---------------- Kernel A2: merge partials + slaev2 eigh + lcc ----------------
__global__ __launch_bounds__(128)
void knn_merge_geom_kernel(const float* __restrict__ xg, float* __restrict__ out)
{
    const int pt = blockIdx.x * 128 + threadIdx.x;
    const int b  = pt >> 12;
    const int n  = pt & (NN - 1);
    const float2* xb = reinterpret_cast<const float2*>(xg) + (size_t)b * NN;

    float pd[20]; int pi[20];
    {
        const float* gp = g_pd + (size_t)pt * 20;
        const int*   gi = g_pi + (size_t)pt * 20;
        #pragma unroll
        for (int j = 0; j < 20; ++j) { pd[j] = gp[j]; pi[j] = gi[j]; }
    }

    int nb[5];
    unsigned used = 0;
    #pragma unroll
    for (int k = 0; k < 5; ++k) {
        float best = 3.5e38f; int bidx = 0x7fffffff; int bj = 0;
        #pragma unroll
        for (int j = 0; j < 20; ++j) {
            bool freej = !((used >> j) & 1u);
            float dj = pd[j]; int ij = pi[j];
            if (freej && (dj < best || (dj == best && ij < bidx))) {
                best = dj; bidx = ij; bj = j;
            }
        }
        used |= 1u << bj;
        nb[k] = bidx;
    }

    const float qx = xb[n].x, qy = xb[n].y;
    float rx[5], ry[5];
    #pragma unroll
    for (int k = 0; k < 5; ++k) {
        float2 p = xb[nb[k]];
        rx[k] = __fsub_rn(p.x, qx);
        ry[k] = __fsub_rn(p.y, qy);
    }
    float sxs = __fadd_rn(__fadd_rn(__fadd_rn(__fadd_rn(rx[0], rx[1]), rx[2]), rx[3]), rx[4]);
    float sys = __fadd_rn(__fadd_rn(__fadd_rn(__fadd_rn(ry[0], ry[1]), ry[2]), ry[3]), ry[4]);
    float mx = __fdiv_rn(sxs, 5.0f);
    float my = __fdiv_rn(sys, 5.0f);
    float cx[5], cy[5];
    float sxx = 0.f, sxy = 0.f, syy = 0.f;
    #pragma unroll
    for (int k = 0; k < 5; ++k) {
        cx[k] = __fsub_rn(rx[k], mx);
        cy[k] = __fsub_rn(ry[k], my);
        sxx = __fmaf_rn(cx[k], cx[k], sxx);
        sxy = __fmaf_rn(cx[k], cy[k], sxy);
        syy = __fmaf_rn(cy[k], cy[k], syy);
    }
    float a  = __fadd_rn(__fmul_rn(sxx, 0.25f), 1e-6f);
    float bv = __fmul_rn(sxy, 0.25f);
    float c  = __fadd_rn(__fmul_rn(syy, 0.25f), 1e-6f);

    // ---- LAPACK slaev2 (a,c > 0 => sm > 0 => sgn1 = +1) ----
    float smv = a + c, df = a - c;
    float adf = fabsf(df);
    float tb  = bv + bv;
    float ab  = fabsf(tb);
    float rt;
    if (adf > ab)      { float t = ab / adf; rt = adf * sqrtf(1.f + t*t); }
    else if (adf < ab) { float t = adf / ab; rt = ab * sqrtf(1.f + t*t); }
    else               { rt = ab * 1.4142135623730951f; }
    float rt1 = 0.5f * (smv + rt);
    float acmx, acmn;
    if (fabsf(a) > fabsf(c)) { acmx = a; acmn = c; } else { acmx = c; acmn = a; }
    float rt2 = (acmx / rt1) * acmn - (bv / rt1) * bv;
    float cs; int sgn2;
    if (df >= 0.f) { cs = df + rt; sgn2 = 1; }
    else           { cs = df - rt; sgn2 = -1; }
    float acs = fabsf(cs), cs1, sn1;
    if (acs > ab)       { float ct = -tb / cs; sn1 = 1.f / sqrtf(1.f + ct*ct); cs1 = ct * sn1; }
    else if (ab == 0.f) { cs1 = 1.f; sn1 = 0.f; }
    else                { float tn = -cs / tb; cs1 = 1.f / sqrtf(1.f + tn*tn); sn1 = tn * cs1; }
    if (sgn2 == 1)      { float t = cs1; cs1 = -sn1; sn1 = t; }

    float e0, e1, v00, v10, v01, v11;
    if (rt2 < rt1) { e0 = rt2; e1 = rt1; v00 = -sn1; v10 = cs1; v01 = cs1;  v11 = sn1; }
    else           { e0 = rt1; e1 = rt2; v00 = cs1;  v10 = sn1; v01 = -sn1; v11 = cs1; }

    out[OFF_ANG + pt] = atan2f(v11, v01);
    float sL = sqrtf(fmaxf(e1, 1e-6f));
    float sS = sqrtf(fmaxf(e0, 1e-6f));
    float den = fmaxf(sL, sS) + 1e-6f;
    out[OFF_AX + pt * 2 + 0] = fmaxf(sL / den, 0.2f);
    out[OFF_AX + pt * 2 + 1] = fmaxf(sS / den, 0.2f);

    float* lp = g_lcc + (size_t)pt * 10;
    #pragma unroll
    for (int k = 0; k < 5; ++k) {
        lp[2*k]   = __fmaf_rn(cy[k], v10, __fmul_rn(cx[k], v00));
        lp[2*k+1] = __fmaf_rn(cy[k], v11, __fmul_rn(cx[k], v01));
    }
}

// ---------------- Kernel B: local MLP 2->64->128->64 + max over K ----------------
// 32 points/CTA (160 rows), 512 threads. Ping-pong pipelined k-loops (no MOVs).
#define B_SMEM_FLOATS (27392 + 160*133)
__global__ __launch_bounds__(512)
void local_mlp_kernel(const float* __restrict__ lw1, const float* __restrict__ lb1,
                      const float* __restrict__ lw2, const float* __restrict__ lb2,
                      const float* __restrict__ lw3, const float* __restrict__ lb3)
{
    extern __shared__ float smf[];
    float* w1s  = smf;
    float* b1s  = smf + 128;
    float* w2s  = smf + 192;
    float* b2s  = smf + 8384;
    float* w3s  = smf + 8512;
    float* b3s  = smf + 16704;
    float* lccs = smf + 16768;
    float* h1T  = smf + 17088;   // [64][161]  k-major
    float* h2s  = smf + 27392;   // [160][133]

    const int tid  = threadIdx.x;
    const int base = blockIdx.x * 32;

    for (int i = tid; i < 128;  i += 512) { w1s[i] = lw1[i]; b2s[i] = lb2[i]; }
    for (int i = tid; i < 64;   i += 512) { b1s[i] = lb1[i]; b3s[i] = lb3[i]; }
    for (int i = tid; i < 8192; i += 512) { w2s[i] = lw2[i]; w3s[i] = lw3[i]; }
    if (tid < 320) lccs[tid] = g_lcc[(size_t)base * 10 + tid];
    __syncthreads();

    // stage 1: h1 (160x64) -> h1T[c*161 + r]
    for (int idx = tid; idx < 160 * 64; idx += 512) {
        int r = idx >> 6, c = idx & 63;
        float v = fmaf(lccs[2*r], w1s[c], fmaf(lccs[2*r+1], w1s[64 + c], b1s[c]));
        h1T[c * 161 + r] = fmaxf(v, 0.f);
    }
    __syncthreads();

    const int rg = tid & 31;       // point
    const int cg = tid >> 5;       // 0..15
    const int r0 = rg * 5;

    // stage 2: h2 (160x128), tile 5 rows x 8 cols, ping-pong pipelined
    {
        const int c0 = cg * 8;
        ull acc[5][4];
        ulonglong2 bp0 = *reinterpret_cast<const ulonglong2*>(b2s + c0);
        ulonglong2 bp1 = *reinterpret_cast<const ulonglong2*>(b2s + c0 + 4);
        #pragma unroll
        for (int j = 0; j < 5; ++j) {
            acc[j][0] = bp0.x; acc[j][1] = bp0.y; acc[j][2] = bp1.x; acc[j][3] = bp1.y;
        }
        ull avA[5], avB[5];
        ulonglong2 w0A, w1A, w0B, w1B;
        #pragma unroll
        for (int j = 0; j < 5; ++j) avA[j] = pack2(h1T[r0 + j]);
        w0A = *reinterpret_cast<const ulonglong2*>(w2s + c0);
        w1A = *reinterpret_cast<const ulonglong2*>(w2s + c0 + 4);
        for (int k = 0; k < 64; k += 2) {
            #pragma unroll
            for (int j = 0; j < 5; ++j) avB[j] = pack2(h1T[(k + 1) * 161 + r0 + j]);
            w0B = *reinterpret_cast<const ulonglong2*>(w2s + (k + 1) * 128 + c0);
            w1B = *reinterpret_cast<const ulonglong2*>(w2s + (k + 1) * 128 + c0 + 4);
            #pragma unroll
            for (int j = 0; j < 5; ++j) {
                ffma2(acc[j][0], avA[j], w0A.x);
                ffma2(acc[j][1], avA[j], w0A.y);
                ffma2(acc[j][2], avA[j], w1A.x);
                ffma2(acc[j][3], avA[j], w1A.y);
            }
            #pragma unroll
            for (int j = 0; j < 5; ++j) avA[j] = pack2(h1T[(k + 2) * 161 + r0 + j]);
            w0A = *reinterpret_cast<const ulonglong2*>(w2s + (k + 2) * 128 + c0);
            w1A = *reinterpret_cast<const ulonglong2*>(w2s + (k + 2) * 128 + c0 + 4);
            #pragma unroll
            for (int j = 0; j < 5; ++j) {
                ffma2(acc[j][0], avB[j], w0B.x);
                ffma2(acc[j][1], avB[j], w0B.y);
                ffma2(acc[j][2], avB[j], w1B.x);
                ffma2(acc[j][3], avB[j], w1B.y);
            }
        }
        #pragma unroll
        for (int j = 0; j < 5; ++j) {
            float* hp = h2s + (r0 + j) * 133 + c0;
            #pragma unroll
            for (int i = 0; i < 4; ++i) {
                hp[2*i]   = fmaxf(lo2(acc[j][i]), 0.f);
                hp[2*i+1] = fmaxf(hi2(acc[j][i]), 0.f);
            }
        }
    }
    __syncthreads();

    // stage 3: h3 (160x64), tile 5 rows x 4 cols, ping-pong, fused relu+max
    {
        const int c0 = cg * 4;
        ull acc3[5][2];
        ulonglong2 bp = *reinterpret_cast<const ulonglong2*>(b3s + c0);
        #pragma unroll
        for (int j = 0; j < 5; ++j) { acc3[j][0] = bp.x; acc3[j][1] = bp.y; }
        ull avA[5], avB[5];
        ulonglong2 wA, wB;
        #pragma unroll
        for (int j = 0; j < 5; ++j) avA[j] = pack2(h2s[(r0 + j) * 133]);
        wA = *reinterpret_cast<const ulonglong2*>(w3s + c0);
        for (int k = 0; k < 128; k += 2) {
            #pragma unroll
            for (int j = 0; j < 5; ++j) avB[j] = pack2(h2s[(r0 + j) * 133 + k + 1]);
            wB = *reinterpret_cast<const ulonglong2*>(w3s + (k + 1) * 64 + c0);
            #pragma unroll
            for (int j = 0; j < 5; ++j) {
                ffma2(acc3[j][0], avA[j], wA.x);
                ffma2(acc3[j][1], avA[j], wA.y);
            }
            #pragma unroll
            for (int j = 0; j < 5; ++j) avA[j] = pack2(h2s[(r0 + j) * 133 + k + 2]);
            wA = *reinterpret_cast<const ulonglong2*>(w3s + (k + 2) * 64 + c0);
            #pragma unroll
            for (int j = 0; j < 5; ++j) {
                ffma2(acc3[j][0], avB[j], wB.x);
                ffma2(acc3[j][1], avB[j], wB.y);
            }
        }
        float4 o;
        float m0 = 0.f, m1 = 0.f, m2 = 0.f, m3 = 0.f;   // relu floor
        #pragma unroll
        for (int j = 0; j < 5; ++j) {
            m0 = fmaxf(m0, lo2(acc3[j][0]));
            m1 = fmaxf(m1, hi2(acc3[j][0]));
            m2 = fmaxf(m2, lo2(acc3[j][1]));
            m3 = fmaxf(m3, hi2(acc3[j][1]));
        }
        o.x = m0; o.y = m1; o.z = m2; o.w = m3;
        *reinterpret_cast<float4*>(g_lf + (size_t)(base + rg) * 64 + c0) = o;
    }
}

// ---------------- Kernel C: BOTH heads, 128 points/CTA, 512 threads ----------------
// NEW tile: 4 points (p0+32j) x 8 cols; k-paired LDS.64 activations; ping-pong.
#define INSTRIDE 70
#define HSTRIDE  134

// compute one k-pair from buffers (a: float2[4], w: ulonglong2[4] = {w_k lo, w_k hi, w_k1 lo, w_k1 hi})
#define HB_PAIR(aArr, wArr)                                              \
    { _Pragma("unroll") for (int j = 0; j < 4; ++j) {                    \
        ull alo = pack2(aArr[j].x);                                      \
        ffma2(acc[j][0], alo, wArr[0].x);                                \
        ffma2(acc[j][1], alo, wArr[0].y);                                \
        ffma2(acc[j][2], alo, wArr[1].x);                                \
        ffma2(acc[j][3], alo, wArr[1].y);                                \
      }                                                                  \
      _Pragma("unroll") for (int j = 0; j < 4; ++j) {                    \
        ull ahi = pack2(aArr[j].y);                                      \
        ffma2(acc[j][0], ahi, wArr[2].x);                                \
        ffma2(acc[j][1], ahi, wArr[2].y);                                \
        ffma2(acc[j][2], ahi, wArr[3].x);                                \
        ffma2(acc[j][3], ahi, wArr[3].y);                                \
      } }

#define HB_PREF(aArr, wArr, actPtr, stride, ws, kk)                                             \
    { _Pragma("unroll") for (int j = 0; j < 4; ++j)                                             \
        aArr[j] = *reinterpret_cast<const float2*>(actPtr + (p0 + 32*j) * stride + (kk));       \
      wArr[0] = *reinterpret_cast<const ulonglong2*>(ws + (kk) * 128 + c0);                     \
      wArr[1] = *reinterpret_cast<const ulonglong2*>(ws + (kk) * 128 + c0 + 4);                 \
      wArr[2] = *reinterpret_cast<const ulonglong2*>(ws + (kk + 1) * 128 + c0);                 \
      wArr[3] = *reinterpret_cast<const ulonglong2*>(ws + (kk + 1) * 128 + c0 + 4); }

template<int INDIM>
__device__ __forceinline__ void head_body(
    const float* __restrict__ w1s, const float* __restrict__ b1s,
    const float* __restrict__ w2s, const float* __restrict__ b2s,
    const float* __restrict__ ins, float* __restrict__ hs,
    float* __restrict__ outp, int base, int tid)
{
    const int p0 = tid & 31;         // points p0, p0+32, p0+64, p0+96
    const int c0 = (tid >> 5) * 8;   // warp-uniform column base

    // stage 1: 128 x INDIM -> 128
    {
        ull acc[4][4];
        ulonglong2 b0 = *reinterpret_cast<const ulonglong2*>(b1s + c0);
        ulonglong2 b1 = *reinterpret_cast<const ulonglong2*>(b1s + c0 + 4);
        #pragma unroll
        for (int j = 0; j < 4; ++j) {
            acc[j][0] = b0.x; acc[j][1] = b0.y; acc[j][2] = b1.x; acc[j][3] = b1.y;
        }
        float2 aA[4], aB[4];
        ulonglong2 wA[4], wB[4];
        HB_PREF(aA, wA, ins, INSTRIDE, w1s, 0)
        for (int k = 0; k < 64; k += 4) {
            HB_PREF(aB, wB, ins, INSTRIDE, w1s, k + 2)
            HB_PAIR(aA, wA)
            // last iter prefetches rows 64,65: inside w1s region (8448) / ins rows (stride 70)
            HB_PREF(aA, wA, ins, INSTRIDE, w1s, k + 4)
            HB_PAIR(aB, wB)
        }
        if (INDIM == 66) { HB_PAIR(aA, wA) }   // pair (64,65) already in A
        #pragma unroll
        for (int j = 0; j < 4; ++j) {
            float* hp = hs + (p0 + 32*j) * HSTRIDE + c0;
            #pragma unroll
            for (int i = 0; i < 4; ++i) {
                float2 v = make_float2(fmaxf(lo2(acc[j][i]), 0.f), fmaxf(hi2(acc[j][i]), 0.f));
                *reinterpret_cast<float2*>(hp + 2*i) = v;
            }
        }
    }
    __syncthreads();

    // stage 2: 128 x 128 -> 128
    {
        ull acc[4][4];
        ulonglong2 b0 = *reinterpret_cast<const ulonglong2*>(b2s + c0);
        ulonglong2 b1 = *reinterpret_cast<const ulonglong2*>(b2s + c0 + 4);
        #pragma unroll
        for (int j = 0; j < 4; ++j) {
            acc[j][0] = b0.x; acc[j][1] = b0.y; acc[j][2] = b1.x; acc[j][3] = b1.y;
        }
        float2 aA[4], aB[4];
        ulonglong2 wA[4], wB[4];
        HB_PREF(aA, wA, hs, HSTRIDE, w2s, 0)
        for (int k = 0; k < 128; k += 4) {
            HB_PREF(aB, wB, hs, HSTRIDE, w2s, k + 2)
            HB_PAIR(aA, wA)
            // last iter prefetches w2s rows 128,129 -> lands in b2s/ins (allocated), unused
            HB_PREF(aA, wA, hs, HSTRIDE, w2s, k + 4)
            HB_PAIR(aB, wB)
        }
        #pragma unroll
        for (int j = 0; j < 4; ++j) {
            float* op = outp + (size_t)(base + p0 + 32*j) * 128 + c0;
            #pragma unroll
            for (int i = 0; i < 4; ++i) {
                float2 v = make_float2(fmaxf(lo2(acc[j][i]), 0.f), fmaxf(hi2(acc[j][i]), 0.f));
                *reinterpret_cast<float2*>(op + 2*i) = v;
            }
        }
    }
}

// smem: w1s 8448 | b1s 128 | w2s 16384 | b2s 128 | ins 128*70 | hs 128*134
#define H_SMEM_FLOATS (8448 + 128 + 16384 + 128 + 128*INSTRIDE + 128*HSTRIDE)
__global__ __launch_bounds__(512)
void head2_kernel(const float* __restrict__ xg,
                  const float* __restrict__ cw1, const float* __restrict__ cb1,
                  const float* __restrict__ cw2, const float* __restrict__ cb2,
                  const float* __restrict__ tw1, const float* __restrict__ tb1,
                  const float* __restrict__ tw2, const float* __restrict__ tb2,
                  float* __restrict__ outg)
{
    extern __shared__ float smf[];
    float* w1s = smf;
    float* b1s = smf + 8448;
    float* w2s = smf + 8576;
    float* b2s = smf + 24960;
    float* ins = smf + 25088;                      // [128][70]
    float* hs  = smf + 25088 + 128*INSTRIDE;       // [128][134]

    const int head = blockIdx.y;
    const float* w1 = head ? tw1 : cw1;
    const float* b1 = head ? tb1 : cb1;
    const float* w2 = head ? tw2 : cw2;
    const float* b2 = head ? tb2 : cb2;
    const int indim = head ? 64 : 66;
    const int xoff  = head ? 0 : 2;
    float* outp = outg + (head ? OFF_TOPO : 0);

    const int tid  = threadIdx.x;
    const int base = blockIdx.x * 128;

    for (int i = tid; i < indim * 128; i += 512) w1s[i] = w1[i];
    for (int i = tid; i < 16384;       i += 512) w2s[i] = w2[i];
    if (tid < 128) { b1s[tid] = b1[tid]; b2s[tid] = b2[tid]; }
    // zero pad cols beyond indim (prefetch reads them; must not be NaN-poisoned? they are
    // multiplied into unused accumulator slots only when INDIM==64 epilogue is skipped --
    // zero anyway for safety of the in-loop boundary prefetch values)
    for (int idx = tid; idx < 128 * 64; idx += 512) {
        int p = idx >> 6, c = idx & 63;
        ins[p * INSTRIDE + xoff + c] = g_lf[(size_t)(base + p) * 64 + c];
    }
    if (tid < 128) {   // pad tail cols [indim, 68) per point to 0 (prefetch safety)
        int p = tid;
        #pragma unroll
        for (int c = 0; c < 4; ++c) ins[p * INSTRIDE + 66 + c] = 0.f;
        if (head) { ins[p * INSTRIDE + 64] = 0.f; ins[p * INSTRIDE + 65] = 0.f; }
    }
    if (!head && tid < 256) {
        int p = tid >> 1, c = tid & 1;
        ins[p * INSTRIDE + c] = xg[(size_t)(base + p) * 2 + c];
    }
    __syncthreads();

    if (head) head_body<64>(w1s, b1s, w2s, b2s, ins, hs, outp, base, tid);
    else      head_body<66>(w1s, b1s, w2s, b2s, ins, hs, outp, base, tid);
}

// ---------------- launch ----------------
extern "C" void kernel_launch(void* const* d_in, const int* in_sizes, int n_in,
                              void* d_out, int out_size)
{
    (void)in_sizes; (void)n_in; (void)out_size;
    const float* x   = (const float*)d_in[0];
    const float* lw1 = (const float*)d_in[1];
    const float* lb1 = (const float*)d_in[2];
    const float* lw2 = (const float*)d_in[3];
    const float* lb2 = (const float*)d_in[4];
    const float* lw3 = (const float*)d_in[5];
    const float* lb3 = (const float*)d_in[6];
    const float* cw1 = (const float*)d_in[7];
    const float* cb1 = (const float*)d_in[8];
    const float* cw2 = (const float*)d_in[9];
    const float* cb2 = (const float*)d_in[10];
    const float* tw1 = (const float*)d_in[11];
    const float* tb1 = (const float*)d_in[12];
    const float* tw2 = (const float*)d_in[13];
    const float* tb2 = (const float*)d_in[14];
    float* out = (float*)d_out;

    const int smB = B_SMEM_FLOATS * 4;
    const int smH = H_SMEM_FLOATS * 4;
    cudaFuncSetAttribute(local_mlp_kernel, cudaFuncAttributeMaxDynamicSharedMemorySize, smB);
    cudaFuncSetAttribute(head2_kernel,     cudaFuncAttributeMaxDynamicSharedMemorySize, smH);

    knn_part_kernel<<<dim3(NN/128, SLICES, 8), 128>>>(x);
    knn_merge_geom_kernel<<<NPTS/128, 128>>>(x, out);
    local_mlp_kernel<<<NPTS/32, 512, smB>>>(lw1, lb1, lw2, lb2, lw3, lb3);
    head2_kernel<<<dim3(NPTS/128, 2), 512, smH>>>(x, cw1, cb1, cw2, cb2,
                                                  tw1, tb1, tw2, tb2, out);
}